// round 10
// baseline (speedup 1.0000x reference)
#include <cuda_runtime.h>
#include <cuda_bf16.h>
#include <math.h>
#include <stdint.h>

// ---------------------------------------------------------------------------
//   xq: (1024, 8, 640)   xk/xv: (8, 1024, 640)   mask: (8, 1024) int32 (bool)
//   Wq/Wk/Wv/Wp: (640,640), biases (640)
//   out: (1024, 8, 640) fp32, attn_save: (8, 1024) fp32
// ---------------------------------------------------------------------------
#define NQ   1024
#define BB   8
#define MM   1024
#define CC   640
#define RR   (NQ * BB)
#define EPS_OT 0.05f
#define N_ITERS 100

#define AP   40     // smem pitch (bf16) for NT tiles, K-tile 32 + 8 pad
#define XAP  136    // gemm_x A tile pitch: n=128 + 8
#define XBP  72     // gemm_x B tile pitch: c=64 + 8

#define NBLK 148    // persistent Sinkhorn grid (<= SM count, wave-1 resident)

// ---------------- static device scratch (allocation-free rule) -------------
__device__ float g_q  [RR * CC];
__device__ float g_k  [RR * CC];
__device__ float g_v  [RR * CC];
__device__ float g_x  [RR * CC];
__device__ float g_sim[(size_t)BB * MM * NQ];
__device__ float g_Kx [(size_t)BB * MM * NQ];
__device__ float g_a  [BB * MM];
__device__ float g_b  [BB * NQ];
__device__ float g_mu [BB * MM];

__device__ unsigned g_bar_count = 0;
__device__ volatile unsigned g_bar_sense = 0;

// ---------------------------------------------------------------------------
// MMA / ldmatrix helpers
// ---------------------------------------------------------------------------
__device__ __forceinline__ uint32_t s2u(const void* p) {
    return (uint32_t)__cvta_generic_to_shared(p);
}
__device__ __forceinline__ void mma16816(float* d, const uint32_t* a, const uint32_t* b) {
    asm volatile(
        "mma.sync.aligned.m16n8k16.row.col.f32.bf16.bf16.f32 "
        "{%0,%1,%2,%3}, {%4,%5,%6,%7}, {%8,%9}, {%0,%1,%2,%3};\n"
        : "+f"(d[0]), "+f"(d[1]), "+f"(d[2]), "+f"(d[3])
        : "r"(a[0]), "r"(a[1]), "r"(a[2]), "r"(a[3]), "r"(b[0]), "r"(b[1]));
}
__device__ __forceinline__ void ldsm4(uint32_t* r, uint32_t a) {
    asm volatile("ldmatrix.sync.aligned.m8n8.x4.shared.b16 {%0,%1,%2,%3}, [%4];\n"
                 : "=r"(r[0]), "=r"(r[1]), "=r"(r[2]), "=r"(r[3]) : "r"(a));
}
__device__ __forceinline__ void ldsm2(uint32_t* r, uint32_t a) {
    asm volatile("ldmatrix.sync.aligned.m8n8.x2.shared.b16 {%0,%1}, [%2];\n"
                 : "=r"(r[0]), "=r"(r[1]) : "r"(a));
}
__device__ __forceinline__ void ldsm4t(uint32_t* r, uint32_t a) {
    asm volatile("ldmatrix.sync.aligned.m8n8.x4.trans.shared.b16 {%0,%1,%2,%3}, [%4];\n"
                 : "=r"(r[0]), "=r"(r[1]), "=r"(r[2]), "=r"(r[3]) : "r"(a));
}
__device__ __forceinline__ void ldsm2t(uint32_t* r, uint32_t a) {
    asm volatile("ldmatrix.sync.aligned.m8n8.x2.trans.shared.b16 {%0,%1}, [%2];\n"
                 : "=r"(r[0]), "=r"(r[1]) : "r"(a));
}
// fp32 -> bf16 hi + residual lo (hi+lo carries 16 mantissa bits; products exact)
__device__ __forceinline__ void split2(float f, __nv_bfloat16& h, __nv_bfloat16& l) {
    h = __float2bfloat16(f);
    l = __float2bfloat16(f - __bfloat162float(h));
}
__device__ __forceinline__ void store4(__nv_bfloat16* H, __nv_bfloat16* L, int base, float4 v) {
    __nv_bfloat16 h0,l0,h1,l1,h2,l2,h3,l3;
    split2(v.x,h0,l0); split2(v.y,h1,l1); split2(v.z,h2,l2); split2(v.w,h3,l3);
    __nv_bfloat162 a; a.x=h0; a.y=h1; __nv_bfloat162 b; b.x=h2; b.y=h3;
    __nv_bfloat162 c; c.x=l0; c.y=l1; __nv_bfloat162 d; d.x=l2; d.y=l3;
    *(__nv_bfloat162*)(H + base)     = a;
    *(__nv_bfloat162*)(H + base + 2) = b;
    *(__nv_bfloat162*)(L + base)     = c;
    *(__nv_bfloat162*)(L + base + 2) = d;
}

// NT mma phase over one BK=32 smem tile: A[128][32] x B[64][32] -> d[2][4][4]
__device__ __forceinline__ void mma_phase_nt(
    const __nv_bfloat16* Ah, const __nv_bfloat16* Al,
    const __nv_bfloat16* Bh, const __nv_bfloat16* Bl,
    int wm, int wn, int lane, float d[2][4][4])
{
#pragma unroll
    for (int ks = 0; ks < 32; ks += 16) {
        uint32_t ah[2][4], al[2][4], bh[4][2], bl[4][2];
#pragma unroll
        for (int i = 0; i < 2; i++) {
            int row = wm + i * 16 + (lane & 15);
            int col = ks + (lane >> 4) * 8;
            uint32_t off = (uint32_t)(row * AP + col) * 2;
            ldsm4(ah[i], s2u(Ah) + off);
            ldsm4(al[i], s2u(Al) + off);
        }
#pragma unroll
        for (int j = 0; j < 4; j++) {
            int row = wn + j * 8 + (lane & 7);
            int col = ks + ((lane >> 3) & 1) * 8;
            uint32_t off = (uint32_t)(row * AP + col) * 2;
            ldsm2(bh[j], s2u(Bh) + off);
            ldsm2(bl[j], s2u(Bl) + off);
        }
#pragma unroll
        for (int i = 0; i < 2; i++)
#pragma unroll
            for (int j = 0; j < 4; j++) {
                mma16816(d[i][j], ah[i], bh[j]);
                mma16816(d[i][j], ah[i], bl[j]);
                mma16816(d[i][j], al[i], bh[j]);
            }
    }
}

// ---------------------------------------------------------------------------
// Projection GEMM via tensor cores:
// out[r,j] = sum_c A[r,c] * W[j,c] + bias[j]    (M=8192, N=640, K=640)
// ---------------------------------------------------------------------------
__global__ __launch_bounds__(256) void gemm_proj_tc(
    const float* __restrict__ A, const float* __restrict__ W,
    const float* __restrict__ bias, float* __restrict__ out)
{
    __shared__ __nv_bfloat16 Ah[128 * AP], Al[128 * AP];
    __shared__ __nv_bfloat16 Bh[64 * AP],  Bl[64 * AP];
    const int tid = threadIdx.x;
    const int m0 = blockIdx.y * 128, n0 = blockIdx.x * 64;
    const int lane = tid & 31, warp = tid >> 5;
    const int wm = (warp & 3) * 32, wn = (warp >> 2) * 32;

    float d[2][4][4];
#pragma unroll
    for (int i = 0; i < 2; i++)
#pragma unroll
        for (int j = 0; j < 4; j++)
#pragma unroll
            for (int e = 0; e < 4; e++) d[i][j][e] = 0.f;

    const int ar = tid >> 1, ak = (tid & 1) * 16;
    const int br = tid >> 2, bk = (tid & 3) * 8;
    const float* Ap = A + (size_t)(m0 + ar) * CC + ak;
    const float* Bp = W + (size_t)(n0 + br) * CC + bk;

    for (int k0 = 0; k0 < CC; k0 += 32) {
#pragma unroll
        for (int i = 0; i < 4; i++)
            store4(Ah, Al, ar * AP + ak + i * 4, *(const float4*)(Ap + k0 + i * 4));
#pragma unroll
        for (int i = 0; i < 2; i++)
            store4(Bh, Bl, br * AP + bk + i * 4, *(const float4*)(Bp + k0 + i * 4));
        __syncthreads();
        mma_phase_nt(Ah, Al, Bh, Bl, wm, wn, lane, d);
        __syncthreads();
    }

#pragma unroll
    for (int i = 0; i < 2; i++) {
        int r0 = m0 + wm + i * 16 + (lane >> 2);
#pragma unroll
        for (int j = 0; j < 4; j++) {
            int c = n0 + wn + j * 8 + (lane & 3) * 2;
            float2 bi = *(const float2*)(bias + c);
            float2 o0 = { d[i][j][0] + bi.x, d[i][j][1] + bi.y };
            float2 o1 = { d[i][j][2] + bi.x, d[i][j][3] + bi.y };
            *(float2*)(out + (size_t)r0 * CC + c)       = o0;
            *(float2*)(out + (size_t)(r0 + 8) * CC + c) = o1;
        }
    }
}

// ---------------------------------------------------------------------------
// sim GEMM: sim[b,m,n] = sum_c k[b,m,c]*q[n,b,c];  Kx = exp((sim-1)/eps)
// ---------------------------------------------------------------------------
__global__ __launch_bounds__(256) void gemm_sim_tc(
    const float* __restrict__ kb, const float* __restrict__ qb,
    float* __restrict__ sim, float* __restrict__ Kx)
{
    __shared__ __nv_bfloat16 Ah[128 * AP], Al[128 * AP];
    __shared__ __nv_bfloat16 Bh[64 * AP],  Bl[64 * AP];
    const int b = blockIdx.z;
    const int tid = threadIdx.x;
    const int m0 = blockIdx.y * 128, n0 = blockIdx.x * 64;
    const int lane = tid & 31, warp = tid >> 5;
    const int wm = (warp & 3) * 32, wn = (warp >> 2) * 32;

    float d[2][4][4];
#pragma unroll
    for (int i = 0; i < 2; i++)
#pragma unroll
        for (int j = 0; j < 4; j++)
#pragma unroll
            for (int e = 0; e < 4; e++) d[i][j][e] = 0.f;

    const int ar = tid >> 1, ak = (tid & 1) * 16;
    const int br = tid >> 2, bk = (tid & 3) * 8;
    const float* Ap = kb + ((size_t)b * MM + m0 + ar) * CC + ak;
    const float* Bp = qb + (size_t)(n0 + br) * (BB * CC) + (size_t)b * CC + bk;

    for (int k0 = 0; k0 < CC; k0 += 32) {
#pragma unroll
        for (int i = 0; i < 4; i++)
            store4(Ah, Al, ar * AP + ak + i * 4, *(const float4*)(Ap + k0 + i * 4));
#pragma unroll
        for (int i = 0; i < 2; i++)
            store4(Bh, Bl, br * AP + bk + i * 4, *(const float4*)(Bp + k0 + i * 4));
        __syncthreads();
        mma_phase_nt(Ah, Al, Bh, Bl, wm, wn, lane, d);
        __syncthreads();
    }

#pragma unroll
    for (int i = 0; i < 2; i++) {
        int m = m0 + wm + i * 16 + (lane >> 2);
#pragma unroll
        for (int j = 0; j < 4; j++) {
            int n = n0 + wn + j * 8 + (lane & 3) * 2;
            size_t o0 = ((size_t)b * MM + m) * NQ + n;
            size_t o1 = ((size_t)b * MM + m + 8) * NQ + n;
            float2 s0 = { d[i][j][0], d[i][j][1] };
            float2 s1 = { d[i][j][2], d[i][j][3] };
            *(float2*)(sim + o0) = s0;
            *(float2*)(sim + o1) = s1;
            float2 k0v = { expf((s0.x - 1.0f) / EPS_OT), expf((s0.y - 1.0f) / EPS_OT) };
            float2 k1v = { expf((s1.x - 1.0f) / EPS_OT), expf((s1.y - 1.0f) / EPS_OT) };
            *(float2*)(Kx + o0) = k0v;
            *(float2*)(Kx + o1) = k1v;
        }
    }
}

// ---------------------------------------------------------------------------
// x GEMM: x[n,b,c] = b[n] * sum_m (a[m]*Kx[b,m,n]) * v[b,m,c]
// ---------------------------------------------------------------------------
__global__ __launch_bounds__(256) void gemm_x_tc(
    const float* __restrict__ Kx, const float* __restrict__ v,
    const float* __restrict__ a, const float* __restrict__ bvec,
    float* __restrict__ x)
{
    __shared__ __nv_bfloat16 Ah[32 * XAP], Al[32 * XAP];   // [m][n] natural
    __shared__ __nv_bfloat16 Bh[32 * XBP], Bl[32 * XBP];   // [m][c] natural
    const int b = blockIdx.z;
    const int tid = threadIdx.x;
    const int n0 = blockIdx.y * 128, c0 = blockIdx.x * 64;
    const int lane = tid & 31, warp = tid >> 5;
    const int wm = (warp & 3) * 32, wn = (warp >> 2) * 32;

    float d[2][4][4];
#pragma unroll
    for (int i = 0; i < 2; i++)
#pragma unroll
        for (int j = 0; j < 4; j++)
#pragma unroll
            for (int e = 0; e < 4; e++) d[i][j][e] = 0.f;

    const int amm = tid >> 3, ann = (tid & 7) * 16;   // A: 32 m-rows x 128 n
    const int bmm = tid >> 3, bcc = (tid & 7) * 8;    // B: 32 m-rows x 64 c

    for (int m0k = 0; m0k < MM; m0k += 32) {
        float am = a[b * MM + m0k + amm];
        const float* Ap = Kx + ((size_t)b * MM + m0k + amm) * NQ + n0 + ann;
        const float* Bp = v  + ((size_t)b * MM + m0k + bmm) * CC + c0 + bcc;
#pragma unroll
        for (int i = 0; i < 4; i++) {
            float4 vv = *(const float4*)(Ap + i * 4);
            vv.x *= am; vv.y *= am; vv.z *= am; vv.w *= am;
            store4(Ah, Al, amm * XAP + ann + i * 4, vv);
        }
#pragma unroll
        for (int i = 0; i < 2; i++)
            store4(Bh, Bl, bmm * XBP + bcc + i * 4, *(const float4*)(Bp + i * 4));
        __syncthreads();

#pragma unroll
        for (int ks = 0; ks < 32; ks += 16) {
            uint32_t ah[2][4], al[2][4], bh[4][2], bl[4][2];
#pragma unroll
            for (int i = 0; i < 2; i++) {
                int row = ks + (lane & 7) + ((lane >> 4) << 3);
                int col = wm + i * 16 + ((lane >> 3) & 1) * 8;
                uint32_t off = (uint32_t)(row * XAP + col) * 2;
                ldsm4t(ah[i], s2u(Ah) + off);
                ldsm4t(al[i], s2u(Al) + off);
            }
#pragma unroll
            for (int j = 0; j < 4; j++) {
                int row = ks + (lane & 15);
                int col = wn + j * 8;
                uint32_t off = (uint32_t)(row * XBP + col) * 2;
                ldsm2t(bh[j], s2u(Bh) + off);
                ldsm2t(bl[j], s2u(Bl) + off);
            }
#pragma unroll
            for (int i = 0; i < 2; i++)
#pragma unroll
                for (int j = 0; j < 4; j++) {
                    mma16816(d[i][j], ah[i], bh[j]);
                    mma16816(d[i][j], ah[i], bl[j]);
                    mma16816(d[i][j], al[i], bh[j]);
                }
        }
        __syncthreads();
    }

#pragma unroll
    for (int i = 0; i < 2; i++) {
        int n = n0 + wm + i * 16 + (lane >> 2);
        float bn0 = bvec[b * NQ + n];
        float bn1 = bvec[b * NQ + n + 8];
#pragma unroll
        for (int j = 0; j < 4; j++) {
            int c = c0 + wn + j * 8 + (lane & 3) * 2;
            float2 o0 = { d[i][j][0] * bn0, d[i][j][1] * bn0 };
            float2 o1 = { d[i][j][2] * bn1, d[i][j][3] * bn1 };
            *(float2*)(x + ((size_t)n * BB + b) * CC + c)       = o0;
            *(float2*)(x + ((size_t)(n + 8) * BB + b) * CC + c) = o1;
        }
    }
}

// ---------------------------------------------------------------------------
// l2norm over each 640-element row, in place. One warp per row.
// ---------------------------------------------------------------------------
__global__ __launch_bounds__(256) void l2norm_rows(float* __restrict__ buf)
{
    const int row  = blockIdx.x * 8 + (threadIdx.x >> 5);
    const int lane = threadIdx.x & 31;
    float4* p = (float4*)(buf + (size_t)row * CC);
    float4 vals[5];
    float ss = 0.f;
#pragma unroll
    for (int i = 0; i < 5; i++) {
        vals[i] = p[lane + i * 32];
        ss += vals[i].x*vals[i].x + vals[i].y*vals[i].y
            + vals[i].z*vals[i].z + vals[i].w*vals[i].w;
    }
#pragma unroll
    for (int o = 16; o; o >>= 1) ss += __shfl_xor_sync(0xffffffffu, ss, o);
    float inv = 1.0f / fmaxf(sqrtf(ss), 1e-12f);
#pragma unroll
    for (int i = 0; i < 5; i++) {
        float4 v = vals[i];
        v.x *= inv; v.y *= inv; v.z *= inv; v.w *= inv;
        p[lane + i * 32] = v;
    }
}

// ---------------------------------------------------------------------------
// Sinkhorn prep (mask = int32)
// ---------------------------------------------------------------------------
__global__ __launch_bounds__(1024) void prep(
    const int* __restrict__ mask,
    float* __restrict__ muP,
    float* __restrict__ bvec)
{
    const int b = blockIdx.x;
    const int m = threadIdx.x;
    int v = (mask[b * MM + m] != 0) ? 1 : 0;
    __shared__ int red[32];
    __shared__ int total;
    int s = v;
#pragma unroll
    for (int o = 16; o; o >>= 1) s += __shfl_xor_sync(0xffffffffu, s, o);
    if ((m & 31) == 0) red[m >> 5] = s;
    __syncthreads();
    if (m < 32) {
        int t = red[m];
#pragma unroll
        for (int o = 16; o; o >>= 1) t += __shfl_xor_sync(0xffffffffu, t, o);
        if (m == 0) total = t;
    }
    __syncthreads();
    int cnt = total;
    muP[b * MM + m]  = v ? (1.0f / (float)cnt + 1e-8f) : 0.0f;
    bvec[b * MM + m] = 1.0f;
}

// ---------------------------------------------------------------------------
// Persistent Sinkhorn: one launch, NBLK blocks (all co-resident), manual
// sense-reversal grid barrier. 2 barriers/iter x 100 iters = 200 (even ->
// barrier globals self-restore to 0 for the next graph replay).
// ---------------------------------------------------------------------------
__device__ __forceinline__ void gbar(unsigned* sense)
{
    __threadfence();
    __syncthreads();
    if (threadIdx.x == 0) {
        unsigned s = 1u - *sense;
        *sense = s;
        if (atomicAdd(&g_bar_count, 1u) == NBLK - 1) {
            atomicExch(&g_bar_count, 0u);
            __threadfence();
            g_bar_sense = s;
        } else {
            while (g_bar_sense != s) __nanosleep(64);
        }
    }
    __syncthreads();
}

__global__ __launch_bounds__(256) void sinkhorn_persist(
    const float* __restrict__ Kx,
    const float* __restrict__ muP,
    float* __restrict__ a,
    float* __restrict__ bvec)
{
    __shared__ float sh[1024];
    __shared__ float part[8][32];
    const int bid  = blockIdx.x;
    const int tid  = threadIdx.x;
    const int warp = tid >> 5, lane = tid & 31;
    unsigned sense = 0;
    const float nuP = 1.0f / (float)NQ + 1e-8f;

    // row-phase: blocks 0..143, 18 blocks per batch
    const bool rowActive = (bid < 144);
    const int rb = bid / 18;
    const int ri = bid % 18;

    for (int it = 0; it < N_ITERS; it++) {
        // ---- row phase: a[b,m] = muP / sum_n Kx[b,m,n] * b[n] ----
        if (rowActive) {
            ((float4*)sh)[tid] = ((const float4*)(bvec + rb * NQ))[tid];
            __syncthreads();
            for (int m = ri * 8 + warp; m < MM; m += 144) {
                float mu = muP[rb * MM + m];
                if (mu != 0.f) {
                    const float4* row = (const float4*)(Kx + ((size_t)rb * MM + m) * NQ);
                    float s = 0.f;
#pragma unroll
                    for (int i = 0; i < 8; i++) {
                        float4 kv = row[lane + i * 32];
                        float4 bv = ((const float4*)sh)[lane + i * 32];
                        s += kv.x*bv.x + kv.y*bv.y + kv.z*bv.z + kv.w*bv.w;
                    }
#pragma unroll
                    for (int o = 16; o; o >>= 1) s += __shfl_xor_sync(0xffffffffu, s, o);
                    if (lane == 0) a[rb * MM + m] = mu / s;
                } else if (lane == 0 && it == 0) {
                    a[rb * MM + m] = 0.f;
                }
            }
        }
        gbar(&sense);

        // ---- col phase: b[b,n] = nuP / sum_m a[b,m]*Kx[b,m,n] ----
        for (int u = bid; u < 256; u += NBLK) {
            const int cb = u >> 5;
            const int n0 = (u & 31) * 32;
            __syncthreads();
            ((float4*)sh)[tid] = ((const float4*)(a + cb * MM))[tid];
            __syncthreads();
            float s = 0.f;
            const float* base = Kx + (size_t)cb * MM * NQ + n0 + lane;
#pragma unroll 4
            for (int m = warp; m < MM; m += 8) {
                float am = sh[m];
                if (am != 0.f) s += am * base[(size_t)m * NQ];
            }
            part[warp][lane] = s;
            __syncthreads();
            if (tid < 32) {
                float t = 0.f;
#pragma unroll
                for (int g = 0; g < 8; g++) t += part[g][lane];
                bvec[cb * NQ + n0 + lane] = (t > 0.f) ? (nuP / t) : 0.f;
            }
        }
        gbar(&sense);
    }
}

// ---------------------------------------------------------------------------
// attn_save[b,m] = mask ? M*Nq * a[m] * sum_n sim*Kx*b[n] : 0
// ---------------------------------------------------------------------------
__global__ __launch_bounds__(256) void attn_kernel(
    const float* __restrict__ sim,
    const float* __restrict__ Kx,
    const float* __restrict__ a,
    const float* __restrict__ bvec,
    const float* __restrict__ muP,
    float* __restrict__ out_attn)
{
    __shared__ float bs[NQ];
    const int blk = blockIdx.x;
    const int b   = blk >> 7;
    const int m   = (blk & 127) * 8 + (threadIdx.x >> 5);
    const int lane = threadIdx.x & 31;
    ((float4*)bs)[threadIdx.x] = ((const float4*)(bvec + b * NQ))[threadIdx.x];
    __syncthreads();
    float mu  = muP[b * MM + m];
    float val = 0.f;
    if (mu != 0.f) {
        size_t off = ((size_t)b * MM + m) * NQ;
        const float4* srow = (const float4*)(sim + off);
        const float4* krow = (const float4*)(Kx + off);
        float s = 0.f;
#pragma unroll
        for (int i = 0; i < 8; i++) {
            float4 sv = srow[lane + i * 32];
            float4 kv = krow[lane + i * 32];
            float4 bv = ((const float4*)bs)[lane + i * 32];
            s += sv.x*kv.x*bv.x + sv.y*kv.y*bv.y + sv.z*kv.z*bv.z + sv.w*kv.w*bv.w;
        }
#pragma unroll
        for (int o = 16; o; o >>= 1) s += __shfl_xor_sync(0xffffffffu, s, o);
        val = (float)(MM) * (float)(NQ) * a[b * MM + m] * s;
    }
    if (lane == 0) out_attn[b * MM + m] = val;
}

// ---------------------------------------------------------------------------
extern "C" void kernel_launch(void* const* d_in, const int* in_sizes, int n_in,
                              void* d_out, int out_size)
{
    const float* xq = (const float*)d_in[0];
    const float* xk = (const float*)d_in[1];
    const float* xv = (const float*)d_in[2];
    const int*   mask = (const int*)d_in[3];
    const float* Wq = (const float*)d_in[4];
    const float* bq = (const float*)d_in[5];
    const float* Wk = (const float*)d_in[6];
    const float* bk = (const float*)d_in[7];
    const float* Wv = (const float*)d_in[8];
    const float* bv = (const float*)d_in[9];
    const float* Wp = (const float*)d_in[10];
    const float* bp = (const float*)d_in[11];

    float* out  = (float*)d_out;
    float* attn = out + (size_t)RR * CC;

    float *q, *k, *v, *x, *sim, *Kx, *a, *b, *mu;
    cudaGetSymbolAddress((void**)&q,   g_q);
    cudaGetSymbolAddress((void**)&k,   g_k);
    cudaGetSymbolAddress((void**)&v,   g_v);
    cudaGetSymbolAddress((void**)&x,   g_x);
    cudaGetSymbolAddress((void**)&sim, g_sim);
    cudaGetSymbolAddress((void**)&Kx,  g_Kx);
    cudaGetSymbolAddress((void**)&a,   g_a);
    cudaGetSymbolAddress((void**)&b,   g_b);
    cudaGetSymbolAddress((void**)&mu,  g_mu);

    dim3 gP(CC / 64, RR / 128);   // (10, 64)

    gemm_proj_tc<<<gP, 256>>>(xq, Wq, bq, q);
    gemm_proj_tc<<<gP, 256>>>(xk, Wk, bk, k);
    gemm_proj_tc<<<gP, 256>>>(xv, Wv, bv, v);
    l2norm_rows<<<RR / 8, 256>>>(q);
    l2norm_rows<<<RR / 8, 256>>>(k);
    prep<<<BB, 1024>>>(mask, mu, b);

    gemm_sim_tc<<<dim3(NQ / 64, MM / 128, BB), 256>>>(k, q, sim, Kx);

    sinkhorn_persist<<<NBLK, 256>>>(Kx, mu, a, b);

    attn_kernel<<<(BB * MM) / 8, 256>>>(sim, Kx, a, b, mu, attn);
    gemm_x_tc<<<dim3(CC / 64, NQ / 128, BB), 256>>>(Kx, v, a, b, x);
    gemm_proj_tc<<<gP, 256>>>(x, Wp, bp, out);
}

// round 12
// speedup vs baseline: 1.1811x; 1.1811x over previous
#include <cuda_runtime.h>
#include <cuda_bf16.h>
#include <math.h>
#include <stdint.h>

// ---------------------------------------------------------------------------
//   xq: (1024, 8, 640)   xk/xv: (8, 1024, 640)   mask: (8, 1024) int32 (bool)
//   Wq/Wk/Wv/Wp: (640,640), biases (640)
//   out: (1024, 8, 640) fp32, attn_save: (8, 1024) fp32
// ---------------------------------------------------------------------------
#define NQ   1024
#define BB   8
#define MM   1024
#define CC   640
#define RR   (NQ * BB)
#define EPS_OT 0.05f
#define N_ITERS 100

#define AP   40     // smem pitch (bf16) for NT tiles, K-tile 32 + 8 pad
#define XAP  136    // gemm_x A tile pitch: n=128 + 8
#define XBP  72     // gemm_x B tile pitch: c=64 + 8

// ---------------- static device scratch (allocation-free rule) -------------
__device__ float g_q  [RR * CC];
__device__ float g_k  [RR * CC];
__device__ float g_v  [RR * CC];
__device__ float g_x  [RR * CC];
__device__ float g_sim[(size_t)BB * MM * NQ];
__device__ float g_Kx [(size_t)BB * MM * NQ];
__device__ float g_a  [BB * MM];
__device__ float g_b  [BB * NQ];
__device__ float g_mu [BB * MM];

// ---------------------------------------------------------------------------
// MMA / ldmatrix helpers
// ---------------------------------------------------------------------------
__device__ __forceinline__ uint32_t s2u(const void* p) {
    return (uint32_t)__cvta_generic_to_shared(p);
}
__device__ __forceinline__ void mma16816(float* d, const uint32_t* a, const uint32_t* b) {
    asm volatile(
        "mma.sync.aligned.m16n8k16.row.col.f32.bf16.bf16.f32 "
        "{%0,%1,%2,%3}, {%4,%5,%6,%7}, {%8,%9}, {%0,%1,%2,%3};\n"
        : "+f"(d[0]), "+f"(d[1]), "+f"(d[2]), "+f"(d[3])
        : "r"(a[0]), "r"(a[1]), "r"(a[2]), "r"(a[3]), "r"(b[0]), "r"(b[1]));
}
__device__ __forceinline__ void ldsm4(uint32_t* r, uint32_t a) {
    asm volatile("ldmatrix.sync.aligned.m8n8.x4.shared.b16 {%0,%1,%2,%3}, [%4];\n"
                 : "=r"(r[0]), "=r"(r[1]), "=r"(r[2]), "=r"(r[3]) : "r"(a));
}
__device__ __forceinline__ void ldsm2(uint32_t* r, uint32_t a) {
    asm volatile("ldmatrix.sync.aligned.m8n8.x2.shared.b16 {%0,%1}, [%2];\n"
                 : "=r"(r[0]), "=r"(r[1]) : "r"(a));
}
__device__ __forceinline__ void ldsm4t(uint32_t* r, uint32_t a) {
    asm volatile("ldmatrix.sync.aligned.m8n8.x4.trans.shared.b16 {%0,%1,%2,%3}, [%4];\n"
                 : "=r"(r[0]), "=r"(r[1]), "=r"(r[2]), "=r"(r[3]) : "r"(a));
}
__device__ __forceinline__ void ldsm2t(uint32_t* r, uint32_t a) {
    asm volatile("ldmatrix.sync.aligned.m8n8.x2.trans.shared.b16 {%0,%1}, [%2];\n"
                 : "=r"(r[0]), "=r"(r[1]) : "r"(a));
}
// fp32 -> bf16 hi + residual lo (hi+lo carries 16 mantissa bits; products exact)
__device__ __forceinline__ void split2(float f, __nv_bfloat16& h, __nv_bfloat16& l) {
    h = __float2bfloat16(f);
    l = __float2bfloat16(f - __bfloat162float(h));
}
__device__ __forceinline__ void store4(__nv_bfloat16* H, __nv_bfloat16* L, int base, float4 v) {
    __nv_bfloat16 h0,l0,h1,l1,h2,l2,h3,l3;
    split2(v.x,h0,l0); split2(v.y,h1,l1); split2(v.z,h2,l2); split2(v.w,h3,l3);
    __nv_bfloat162 a; a.x=h0; a.y=h1; __nv_bfloat162 b; b.x=h2; b.y=h3;
    __nv_bfloat162 c; c.x=l0; c.y=l1; __nv_bfloat162 d; d.x=l2; d.y=l3;
    *(__nv_bfloat162*)(H + base)     = a;
    *(__nv_bfloat162*)(H + base + 2) = b;
    *(__nv_bfloat162*)(L + base)     = c;
    *(__nv_bfloat162*)(L + base + 2) = d;
}

// NT mma phase over one BK=32 smem tile: A[128][32] x B[64][32] -> d[2][4][4]
__device__ __forceinline__ void mma_phase_nt(
    const __nv_bfloat16* Ah, const __nv_bfloat16* Al,
    const __nv_bfloat16* Bh, const __nv_bfloat16* Bl,
    int wm, int wn, int lane, float d[2][4][4])
{
#pragma unroll
    for (int ks = 0; ks < 32; ks += 16) {
        uint32_t ah[2][4], al[2][4], bh[4][2], bl[4][2];
#pragma unroll
        for (int i = 0; i < 2; i++) {
            int row = wm + i * 16 + (lane & 15);
            int col = ks + (lane >> 4) * 8;
            uint32_t off = (uint32_t)(row * AP + col) * 2;
            ldsm4(ah[i], s2u(Ah) + off);
            ldsm4(al[i], s2u(Al) + off);
        }
#pragma unroll
        for (int j = 0; j < 4; j++) {
            int row = wn + j * 8 + (lane & 7);
            int col = ks + ((lane >> 3) & 1) * 8;
            uint32_t off = (uint32_t)(row * AP + col) * 2;
            ldsm2(bh[j], s2u(Bh) + off);
            ldsm2(bl[j], s2u(Bl) + off);
        }
#pragma unroll
        for (int i = 0; i < 2; i++)
#pragma unroll
            for (int j = 0; j < 4; j++) {
                mma16816(d[i][j], ah[i], bh[j]);
                mma16816(d[i][j], ah[i], bl[j]);
                mma16816(d[i][j], al[i], bh[j]);
            }
    }
}

// ---------------------------------------------------------------------------
// Projection GEMM via tensor cores:
// out[r,j] = sum_c A[r,c] * W[j,c] + bias[j]    (M=8192, N=640, K=640)
// ---------------------------------------------------------------------------
__global__ __launch_bounds__(256) void gemm_proj_tc(
    const float* __restrict__ A, const float* __restrict__ W,
    const float* __restrict__ bias, float* __restrict__ out)
{
    __shared__ __nv_bfloat16 Ah[128 * AP], Al[128 * AP];
    __shared__ __nv_bfloat16 Bh[64 * AP],  Bl[64 * AP];
    const int tid = threadIdx.x;
    const int m0 = blockIdx.y * 128, n0 = blockIdx.x * 64;
    const int lane = tid & 31, warp = tid >> 5;
    const int wm = (warp & 3) * 32, wn = (warp >> 2) * 32;

    float d[2][4][4];
#pragma unroll
    for (int i = 0; i < 2; i++)
#pragma unroll
        for (int j = 0; j < 4; j++)
#pragma unroll
            for (int e = 0; e < 4; e++) d[i][j][e] = 0.f;

    const int ar = tid >> 1, ak = (tid & 1) * 16;
    const int br = tid >> 2, bk = (tid & 3) * 8;
    const float* Ap = A + (size_t)(m0 + ar) * CC + ak;
    const float* Bp = W + (size_t)(n0 + br) * CC + bk;

    for (int k0 = 0; k0 < CC; k0 += 32) {
#pragma unroll
        for (int i = 0; i < 4; i++)
            store4(Ah, Al, ar * AP + ak + i * 4, *(const float4*)(Ap + k0 + i * 4));
#pragma unroll
        for (int i = 0; i < 2; i++)
            store4(Bh, Bl, br * AP + bk + i * 4, *(const float4*)(Bp + k0 + i * 4));
        __syncthreads();
        mma_phase_nt(Ah, Al, Bh, Bl, wm, wn, lane, d);
        __syncthreads();
    }

#pragma unroll
    for (int i = 0; i < 2; i++) {
        int r0 = m0 + wm + i * 16 + (lane >> 2);
#pragma unroll
        for (int j = 0; j < 4; j++) {
            int c = n0 + wn + j * 8 + (lane & 3) * 2;
            float2 bi = *(const float2*)(bias + c);
            float2 o0 = { d[i][j][0] + bi.x, d[i][j][1] + bi.y };
            float2 o1 = { d[i][j][2] + bi.x, d[i][j][3] + bi.y };
            *(float2*)(out + (size_t)r0 * CC + c)       = o0;
            *(float2*)(out + (size_t)(r0 + 8) * CC + c) = o1;
        }
    }
}

// ---------------------------------------------------------------------------
// sim GEMM: sim[b,m,n] = sum_c k[b,m,c]*q[n,b,c];  Kx = exp((sim-1)/eps)
// ---------------------------------------------------------------------------
__global__ __launch_bounds__(256) void gemm_sim_tc(
    const float* __restrict__ kb, const float* __restrict__ qb,
    float* __restrict__ sim, float* __restrict__ Kx)
{
    __shared__ __nv_bfloat16 Ah[128 * AP], Al[128 * AP];
    __shared__ __nv_bfloat16 Bh[64 * AP],  Bl[64 * AP];
    const int b = blockIdx.z;
    const int tid = threadIdx.x;
    const int m0 = blockIdx.y * 128, n0 = blockIdx.x * 64;
    const int lane = tid & 31, warp = tid >> 5;
    const int wm = (warp & 3) * 32, wn = (warp >> 2) * 32;

    float d[2][4][4];
#pragma unroll
    for (int i = 0; i < 2; i++)
#pragma unroll
        for (int j = 0; j < 4; j++)
#pragma unroll
            for (int e = 0; e < 4; e++) d[i][j][e] = 0.f;

    const int ar = tid >> 1, ak = (tid & 1) * 16;
    const int br = tid >> 2, bk = (tid & 3) * 8;
    const float* Ap = kb + ((size_t)b * MM + m0 + ar) * CC + ak;
    const float* Bp = qb + (size_t)(n0 + br) * (BB * CC) + (size_t)b * CC + bk;

    for (int k0 = 0; k0 < CC; k0 += 32) {
#pragma unroll
        for (int i = 0; i < 4; i++)
            store4(Ah, Al, ar * AP + ak + i * 4, *(const float4*)(Ap + k0 + i * 4));
#pragma unroll
        for (int i = 0; i < 2; i++)
            store4(Bh, Bl, br * AP + bk + i * 4, *(const float4*)(Bp + k0 + i * 4));
        __syncthreads();
        mma_phase_nt(Ah, Al, Bh, Bl, wm, wn, lane, d);
        __syncthreads();
    }

#pragma unroll
    for (int i = 0; i < 2; i++) {
        int m = m0 + wm + i * 16 + (lane >> 2);
#pragma unroll
        for (int j = 0; j < 4; j++) {
            int n = n0 + wn + j * 8 + (lane & 3) * 2;
            size_t o0 = ((size_t)b * MM + m) * NQ + n;
            size_t o1 = ((size_t)b * MM + m + 8) * NQ + n;
            float2 s0 = { d[i][j][0], d[i][j][1] };
            float2 s1 = { d[i][j][2], d[i][j][3] };
            *(float2*)(sim + o0) = s0;
            *(float2*)(sim + o1) = s1;
            float2 k0v = { expf((s0.x - 1.0f) / EPS_OT), expf((s0.y - 1.0f) / EPS_OT) };
            float2 k1v = { expf((s1.x - 1.0f) / EPS_OT), expf((s1.y - 1.0f) / EPS_OT) };
            *(float2*)(Kx + o0) = k0v;
            *(float2*)(Kx + o1) = k1v;
        }
    }
}

// ---------------------------------------------------------------------------
// x GEMM: x[n,b,c] = b[n] * sum_m (a[m]*Kx[b,m,n]) * v[b,m,c]
// ---------------------------------------------------------------------------
__global__ __launch_bounds__(256) void gemm_x_tc(
    const float* __restrict__ Kx, const float* __restrict__ v,
    const float* __restrict__ a, const float* __restrict__ bvec,
    float* __restrict__ x)
{
    __shared__ __nv_bfloat16 Ah[32 * XAP], Al[32 * XAP];   // [m][n] natural
    __shared__ __nv_bfloat16 Bh[32 * XBP], Bl[32 * XBP];   // [m][c] natural
    const int b = blockIdx.z;
    const int tid = threadIdx.x;
    const int n0 = blockIdx.y * 128, c0 = blockIdx.x * 64;
    const int lane = tid & 31, warp = tid >> 5;
    const int wm = (warp & 3) * 32, wn = (warp >> 2) * 32;

    float d[2][4][4];
#pragma unroll
    for (int i = 0; i < 2; i++)
#pragma unroll
        for (int j = 0; j < 4; j++)
#pragma unroll
            for (int e = 0; e < 4; e++) d[i][j][e] = 0.f;

    const int amm = tid >> 3, ann = (tid & 7) * 16;   // A: 32 m-rows x 128 n
    const int bmm = tid >> 3, bcc = (tid & 7) * 8;    // B: 32 m-rows x 64 c

    for (int m0k = 0; m0k < MM; m0k += 32) {
        float am = a[b * MM + m0k + amm];
        const float* Ap = Kx + ((size_t)b * MM + m0k + amm) * NQ + n0 + ann;
        const float* Bp = v  + ((size_t)b * MM + m0k + bmm) * CC + c0 + bcc;
#pragma unroll
        for (int i = 0; i < 4; i++) {
            float4 vv = *(const float4*)(Ap + i * 4);
            vv.x *= am; vv.y *= am; vv.z *= am; vv.w *= am;
            store4(Ah, Al, amm * XAP + ann + i * 4, vv);
        }
#pragma unroll
        for (int i = 0; i < 2; i++)
            store4(Bh, Bl, bmm * XBP + bcc + i * 4, *(const float4*)(Bp + i * 4));
        __syncthreads();

#pragma unroll
        for (int ks = 0; ks < 32; ks += 16) {
            uint32_t ah[2][4], al[2][4], bh[4][2], bl[4][2];
#pragma unroll
            for (int i = 0; i < 2; i++) {
                int row = ks + (lane & 7) + ((lane >> 4) << 3);
                int col = wm + i * 16 + ((lane >> 3) & 1) * 8;
                uint32_t off = (uint32_t)(row * XAP + col) * 2;
                ldsm4t(ah[i], s2u(Ah) + off);
                ldsm4t(al[i], s2u(Al) + off);
            }
#pragma unroll
            for (int j = 0; j < 4; j++) {
                int row = ks + (lane & 15);
                int col = wn + j * 8;
                uint32_t off = (uint32_t)(row * XBP + col) * 2;
                ldsm2t(bh[j], s2u(Bh) + off);
                ldsm2t(bl[j], s2u(Bl) + off);
            }
#pragma unroll
            for (int i = 0; i < 2; i++)
#pragma unroll
                for (int j = 0; j < 4; j++) {
                    mma16816(d[i][j], ah[i], bh[j]);
                    mma16816(d[i][j], ah[i], bl[j]);
                    mma16816(d[i][j], al[i], bh[j]);
                }
        }
        __syncthreads();
    }

#pragma unroll
    for (int i = 0; i < 2; i++) {
        int n = n0 + wm + i * 16 + (lane >> 2);
        float bn0 = bvec[b * NQ + n];
        float bn1 = bvec[b * NQ + n + 8];
#pragma unroll
        for (int j = 0; j < 4; j++) {
            int c = c0 + wn + j * 8 + (lane & 3) * 2;
            float2 o0 = { d[i][j][0] * bn0, d[i][j][1] * bn0 };
            float2 o1 = { d[i][j][2] * bn1, d[i][j][3] * bn1 };
            *(float2*)(x + ((size_t)n * BB + b) * CC + c)       = o0;
            *(float2*)(x + ((size_t)(n + 8) * BB + b) * CC + c) = o1;
        }
    }
}

// ---------------------------------------------------------------------------
// l2norm over each 640-element row, in place. One warp per row.
// ---------------------------------------------------------------------------
__global__ __launch_bounds__(256) void l2norm_rows(float* __restrict__ buf)
{
    const int row  = blockIdx.x * 8 + (threadIdx.x >> 5);
    const int lane = threadIdx.x & 31;
    float4* p = (float4*)(buf + (size_t)row * CC);
    float4 vals[5];
    float ss = 0.f;
#pragma unroll
    for (int i = 0; i < 5; i++) {
        vals[i] = p[lane + i * 32];
        ss += vals[i].x*vals[i].x + vals[i].y*vals[i].y
            + vals[i].z*vals[i].z + vals[i].w*vals[i].w;
    }
#pragma unroll
    for (int o = 16; o; o >>= 1) ss += __shfl_xor_sync(0xffffffffu, ss, o);
    float inv = 1.0f / fmaxf(sqrtf(ss), 1e-12f);
#pragma unroll
    for (int i = 0; i < 5; i++) {
        float4 v = vals[i];
        v.x *= inv; v.y *= inv; v.z *= inv; v.w *= inv;
        p[lane + i * 32] = v;
    }
}

// ---------------------------------------------------------------------------
// Sinkhorn prep (mask = int32); also zeroes a (masked rows stay 0 forever).
// ---------------------------------------------------------------------------
__global__ __launch_bounds__(1024) void prep(
    const int* __restrict__ mask,
    float* __restrict__ muP,
    float* __restrict__ bvec,
    float* __restrict__ a)
{
    const int b = blockIdx.x;
    const int m = threadIdx.x;
    int v = (mask[b * MM + m] != 0) ? 1 : 0;
    __shared__ int red[32];
    __shared__ int total;
    int s = v;
#pragma unroll
    for (int o = 16; o; o >>= 1) s += __shfl_xor_sync(0xffffffffu, s, o);
    if ((m & 31) == 0) red[m >> 5] = s;
    __syncthreads();
    if (m < 32) {
        int t = red[m];
#pragma unroll
        for (int o = 16; o; o >>= 1) t += __shfl_xor_sync(0xffffffffu, t, o);
        if (m == 0) total = t;
    }
    __syncthreads();
    int cnt = total;
    muP[b * MM + m]  = v ? (1.0f / (float)cnt + 1e-8f) : 0.0f;
    bvec[b * MM + m] = 1.0f;
    a[b * MM + m]    = 0.0f;
}

// ---------------------------------------------------------------------------
// Persistent cluster Sinkhorn: one cluster of 8 CTAs per batch (batches are
// independent -> only intra-cluster sync needed; barrier.cluster ~380cyc).
// CTA r of batch b owns rows [r*128, r*128+128) in the row phase and cols
// [r*128, r*128+128) in the col phase. 1024 threads = 32 warps per CTA.
// ---------------------------------------------------------------------------
__global__ __launch_bounds__(1024) __cluster_dims__(8, 1, 1)
void sinkhorn_cluster(
    const float* __restrict__ Kx,
    const float* __restrict__ muP,
    float* __restrict__ a,
    float* __restrict__ bvec)
{
    __shared__ float sh[1024];
    __shared__ float part[32][33];
    const int tid  = threadIdx.x;
    const int warp = tid >> 5, lane = tid & 31;
    const int b = blockIdx.x >> 3;
    const int r = blockIdx.x & 7;
    const float nuP = 1.0f / (float)NQ + 1e-8f;

    for (int it = 0; it < N_ITERS; it++) {
        // ---- row phase: a[b,m] = muP / sum_n Kx[b,m,n]*b[n], m in CTA slice
        sh[tid] = bvec[b * NQ + tid];
        __syncthreads();
#pragma unroll
        for (int rr = 0; rr < 4; rr++) {
            int m = r * 128 + warp * 4 + rr;
            float mu = muP[b * MM + m];
            if (mu != 0.f) {
                const float4* row = (const float4*)(Kx + ((size_t)b * MM + m) * NQ);
                float s = 0.f;
#pragma unroll
                for (int i = 0; i < 8; i++) {
                    float4 kv = row[lane + i * 32];
                    float4 bv = ((const float4*)sh)[lane + i * 32];
                    s += kv.x*bv.x + kv.y*bv.y + kv.z*bv.z + kv.w*bv.w;
                }
#pragma unroll
                for (int o = 16; o; o >>= 1) s += __shfl_xor_sync(0xffffffffu, s, o);
                if (lane == 0) a[b * MM + m] = mu / s;
            }
        }
        __threadfence();
        asm volatile("barrier.cluster.arrive.aligned;" ::: "memory");
        asm volatile("barrier.cluster.wait.aligned;" ::: "memory");
        __syncthreads();

        // ---- col phase: b[b,n] = nuP / sum_m a[b,m]*Kx[b,m,n], n in slice
        sh[tid] = a[b * MM + tid];
        __syncthreads();
        {
            const int slab = warp >> 3;          // 4 slabs of 32 cols
            const int g    = warp & 7;           // 8 m-groups per slab
            const int n0   = r * 128 + slab * 32;
            const float* base = Kx + (size_t)b * MM * NQ + n0 + lane;
            float acc = 0.f;
#pragma unroll 4
            for (int m = g; m < MM; m += 8) {
                float am = sh[m];
                if (am != 0.f) acc += am * base[(size_t)m * NQ];
            }
            part[warp][lane] = acc;
        }
        __syncthreads();
        if (tid < 128) {
            int slab = tid >> 5, c = tid & 31;
            float t = 0.f;
#pragma unroll
            for (int g = 0; g < 8; g++) t += part[slab * 8 + g][c];
            bvec[b * NQ + r * 128 + tid] = (t > 0.f) ? (nuP / t) : 0.f;
        }
        __threadfence();
        asm volatile("barrier.cluster.arrive.aligned;" ::: "memory");
        asm volatile("barrier.cluster.wait.aligned;" ::: "memory");
        __syncthreads();
    }
}

// ---------------------------------------------------------------------------
// attn_save[b,m] = mask ? M*Nq * a[m] * sum_n sim*Kx*b[n] : 0
// ---------------------------------------------------------------------------
__global__ __launch_bounds__(256) void attn_kernel(
    const float* __restrict__ sim,
    const float* __restrict__ Kx,
    const float* __restrict__ a,
    const float* __restrict__ bvec,
    const float* __restrict__ muP,
    float* __restrict__ out_attn)
{
    __shared__ float bs[NQ];
    const int blk = blockIdx.x;
    const int b   = blk >> 7;
    const int m   = (blk & 127) * 8 + (threadIdx.x >> 5);
    const int lane = threadIdx.x & 31;
    ((float4*)bs)[threadIdx.x] = ((const float4*)(bvec + b * NQ))[threadIdx.x];
    __syncthreads();
    float mu  = muP[b * MM + m];
    float val = 0.f;
    if (mu != 0.f) {
        size_t off = ((size_t)b * MM + m) * NQ;
        const float4* srow = (const float4*)(sim + off);
        const float4* krow = (const float4*)(Kx + off);
        float s = 0.f;
#pragma unroll
        for (int i = 0; i < 8; i++) {
            float4 sv = srow[lane + i * 32];
            float4 kv = krow[lane + i * 32];
            float4 bv = ((const float4*)bs)[lane + i * 32];
            s += sv.x*kv.x*bv.x + sv.y*kv.y*bv.y + sv.z*kv.z*bv.z + sv.w*kv.w*bv.w;
        }
#pragma unroll
        for (int o = 16; o; o >>= 1) s += __shfl_xor_sync(0xffffffffu, s, o);
        val = (float)(MM) * (float)(NQ) * a[b * MM + m] * s;
    }
    if (lane == 0) out_attn[b * MM + m] = val;
}

// ---------------------------------------------------------------------------
extern "C" void kernel_launch(void* const* d_in, const int* in_sizes, int n_in,
                              void* d_out, int out_size)
{
    const float* xq = (const float*)d_in[0];
    const float* xk = (const float*)d_in[1];
    const float* xv = (const float*)d_in[2];
    const int*   mask = (const int*)d_in[3];
    const float* Wq = (const float*)d_in[4];
    const float* bq = (const float*)d_in[5];
    const float* Wk = (const float*)d_in[6];
    const float* bk = (const float*)d_in[7];
    const float* Wv = (const float*)d_in[8];
    const float* bv = (const float*)d_in[9];
    const float* Wp = (const float*)d_in[10];
    const float* bp = (const float*)d_in[11];

    float* out  = (float*)d_out;
    float* attn = out + (size_t)RR * CC;

    float *q, *k, *v, *x, *sim, *Kx, *a, *b, *mu;
    cudaGetSymbolAddress((void**)&q,   g_q);
    cudaGetSymbolAddress((void**)&k,   g_k);
    cudaGetSymbolAddress((void**)&v,   g_v);
    cudaGetSymbolAddress((void**)&x,   g_x);
    cudaGetSymbolAddress((void**)&sim, g_sim);
    cudaGetSymbolAddress((void**)&Kx,  g_Kx);
    cudaGetSymbolAddress((void**)&a,   g_a);
    cudaGetSymbolAddress((void**)&b,   g_b);
    cudaGetSymbolAddress((void**)&mu,  g_mu);

    dim3 gP(CC / 64, RR / 128);   // (10, 64)

    gemm_proj_tc<<<gP, 256>>>(xq, Wq, bq, q);
    gemm_proj_tc<<<gP, 256>>>(xk, Wk, bk, k);
    gemm_proj_tc<<<gP, 256>>>(xv, Wv, bv, v);
    l2norm_rows<<<RR / 8, 256>>>(q);
    l2norm_rows<<<RR / 8, 256>>>(k);
    prep<<<BB, 1024>>>(mask, mu, b, a);

    gemm_sim_tc<<<dim3(NQ / 64, MM / 128, BB), 256>>>(k, q, sim, Kx);

    sinkhorn_cluster<<<BB * 8, 1024>>>(Kx, mu, a, b);

    attn_kernel<<<(BB * MM) / 8, 256>>>(sim, Kx, a, b, mu, attn);
    gemm_x_tc<<<dim3(CC / 64, NQ / 128, BB), 256>>>(Kx, v, a, b, x);
    gemm_proj_tc<<<gP, 256>>>(x, Wp, bp, out);
}

// round 14
// speedup vs baseline: 2.4053x; 2.0364x over previous
#include <cuda_runtime.h>
#include <cuda_bf16.h>
#include <math.h>
#include <stdint.h>

// ---------------------------------------------------------------------------
//   xq: (1024, 8, 640)   xk/xv: (8, 1024, 640)   mask: (8, 1024) int32 (bool)
//   Wq/Wk/Wv/Wp: (640,640), biases (640)
//   out: (1024, 8, 640) fp32, attn_save: (8, 1024) fp32
// ---------------------------------------------------------------------------
#define NQ   1024
#define BB   8
#define MM   1024
#define CC   640
#define RR   (NQ * BB)
#define EPS_OT 0.05f
#define N_ITERS 100

#define AP   40     // smem pitch (bf16) for NT tiles, K-tile 32 + 8 pad
#define XAP  136    // gemm_x A tile pitch: n=128 + 8
#define XBP  72     // gemm_x B tile pitch: c=64 + 8

// ---------------- static device scratch (allocation-free rule) -------------
__device__ float g_q  [RR * CC];
__device__ float g_k  [RR * CC];
__device__ float g_v  [RR * CC];
__device__ float g_x  [RR * CC];
__device__ float g_sim[(size_t)BB * MM * NQ];
__device__ float g_Kx [(size_t)BB * MM * NQ];
__device__ float g_a  [BB * MM];
__device__ float g_b  [BB * NQ];
__device__ float g_mu [BB * MM];
__device__ float g_part[256 * NQ];   // per-block partial colsums (1 MB)

// ---------------------------------------------------------------------------
// MMA / ldmatrix helpers
// ---------------------------------------------------------------------------
__device__ __forceinline__ uint32_t s2u(const void* p) {
    return (uint32_t)__cvta_generic_to_shared(p);
}
__device__ __forceinline__ void mma16816(float* d, const uint32_t* a, const uint32_t* b) {
    asm volatile(
        "mma.sync.aligned.m16n8k16.row.col.f32.bf16.bf16.f32 "
        "{%0,%1,%2,%3}, {%4,%5,%6,%7}, {%8,%9}, {%0,%1,%2,%3};\n"
        : "+f"(d[0]), "+f"(d[1]), "+f"(d[2]), "+f"(d[3])
        : "r"(a[0]), "r"(a[1]), "r"(a[2]), "r"(a[3]), "r"(b[0]), "r"(b[1]));
}
__device__ __forceinline__ void ldsm4(uint32_t* r, uint32_t a) {
    asm volatile("ldmatrix.sync.aligned.m8n8.x4.shared.b16 {%0,%1,%2,%3}, [%4];\n"
                 : "=r"(r[0]), "=r"(r[1]), "=r"(r[2]), "=r"(r[3]) : "r"(a));
}
__device__ __forceinline__ void ldsm2(uint32_t* r, uint32_t a) {
    asm volatile("ldmatrix.sync.aligned.m8n8.x2.shared.b16 {%0,%1}, [%2];\n"
                 : "=r"(r[0]), "=r"(r[1]) : "r"(a));
}
__device__ __forceinline__ void ldsm4t(uint32_t* r, uint32_t a) {
    asm volatile("ldmatrix.sync.aligned.m8n8.x4.trans.shared.b16 {%0,%1,%2,%3}, [%4];\n"
                 : "=r"(r[0]), "=r"(r[1]), "=r"(r[2]), "=r"(r[3]) : "r"(a));
}
__device__ __forceinline__ void ldsm2t(uint32_t* r, uint32_t a) {
    asm volatile("ldmatrix.sync.aligned.m8n8.x2.trans.shared.b16 {%0,%1}, [%2];\n"
                 : "=r"(r[0]), "=r"(r[1]) : "r"(a));
}
// fp32 -> bf16 hi + residual lo (hi+lo carries 16 mantissa bits; products exact)
__device__ __forceinline__ void split2(float f, __nv_bfloat16& h, __nv_bfloat16& l) {
    h = __float2bfloat16(f);
    l = __float2bfloat16(f - __bfloat162float(h));
}
__device__ __forceinline__ void store4(__nv_bfloat16* H, __nv_bfloat16* L, int base, float4 v) {
    __nv_bfloat16 h0,l0,h1,l1,h2,l2,h3,l3;
    split2(v.x,h0,l0); split2(v.y,h1,l1); split2(v.z,h2,l2); split2(v.w,h3,l3);
    __nv_bfloat162 a; a.x=h0; a.y=h1; __nv_bfloat162 b; b.x=h2; b.y=h3;
    __nv_bfloat162 c; c.x=l0; c.y=l1; __nv_bfloat162 d; d.x=l2; d.y=l3;
    *(__nv_bfloat162*)(H + base)     = a;
    *(__nv_bfloat162*)(H + base + 2) = b;
    *(__nv_bfloat162*)(L + base)     = c;
    *(__nv_bfloat162*)(L + base + 2) = d;
}

// NT mma phase over one BK=32 smem tile: A[128][32] x B[64][32] -> d[2][4][4]
__device__ __forceinline__ void mma_phase_nt(
    const __nv_bfloat16* Ah, const __nv_bfloat16* Al,
    const __nv_bfloat16* Bh, const __nv_bfloat16* Bl,
    int wm, int wn, int lane, float d[2][4][4])
{
#pragma unroll
    for (int ks = 0; ks < 32; ks += 16) {
        uint32_t ah[2][4], al[2][4], bh[4][2], bl[4][2];
#pragma unroll
        for (int i = 0; i < 2; i++) {
            int row = wm + i * 16 + (lane & 15);
            int col = ks + (lane >> 4) * 8;
            uint32_t off = (uint32_t)(row * AP + col) * 2;
            ldsm4(ah[i], s2u(Ah) + off);
            ldsm4(al[i], s2u(Al) + off);
        }
#pragma unroll
        for (int j = 0; j < 4; j++) {
            int row = wn + j * 8 + (lane & 7);
            int col = ks + ((lane >> 3) & 1) * 8;
            uint32_t off = (uint32_t)(row * AP + col) * 2;
            ldsm2(bh[j], s2u(Bh) + off);
            ldsm2(bl[j], s2u(Bl) + off);
        }
#pragma unroll
        for (int i = 0; i < 2; i++)
#pragma unroll
            for (int j = 0; j < 4; j++) {
                mma16816(d[i][j], ah[i], bh[j]);
                mma16816(d[i][j], ah[i], bl[j]);
                mma16816(d[i][j], al[i], bh[j]);
            }
    }
}

// ---------------------------------------------------------------------------
// Projection GEMM via tensor cores:
// out[r,j] = sum_c A[r,c] * W[j,c] + bias[j]    (M=8192, N=640, K=640)
// ---------------------------------------------------------------------------
__global__ __launch_bounds__(256) void gemm_proj_tc(
    const float* __restrict__ A, const float* __restrict__ W,
    const float* __restrict__ bias, float* __restrict__ out)
{
    __shared__ __nv_bfloat16 Ah[128 * AP], Al[128 * AP];
    __shared__ __nv_bfloat16 Bh[64 * AP],  Bl[64 * AP];
    const int tid = threadIdx.x;
    const int m0 = blockIdx.y * 128, n0 = blockIdx.x * 64;
    const int lane = tid & 31, warp = tid >> 5;
    const int wm = (warp & 3) * 32, wn = (warp >> 2) * 32;

    float d[2][4][4];
#pragma unroll
    for (int i = 0; i < 2; i++)
#pragma unroll
        for (int j = 0; j < 4; j++)
#pragma unroll
            for (int e = 0; e < 4; e++) d[i][j][e] = 0.f;

    const int ar = tid >> 1, ak = (tid & 1) * 16;
    const int br = tid >> 2, bk = (tid & 3) * 8;
    const float* Ap = A + (size_t)(m0 + ar) * CC + ak;
    const float* Bp = W + (size_t)(n0 + br) * CC + bk;

    for (int k0 = 0; k0 < CC; k0 += 32) {
#pragma unroll
        for (int i = 0; i < 4; i++)
            store4(Ah, Al, ar * AP + ak + i * 4, *(const float4*)(Ap + k0 + i * 4));
#pragma unroll
        for (int i = 0; i < 2; i++)
            store4(Bh, Bl, br * AP + bk + i * 4, *(const float4*)(Bp + k0 + i * 4));
        __syncthreads();
        mma_phase_nt(Ah, Al, Bh, Bl, wm, wn, lane, d);
        __syncthreads();
    }

#pragma unroll
    for (int i = 0; i < 2; i++) {
        int r0 = m0 + wm + i * 16 + (lane >> 2);
#pragma unroll
        for (int j = 0; j < 4; j++) {
            int c = n0 + wn + j * 8 + (lane & 3) * 2;
            float2 bi = *(const float2*)(bias + c);
            float2 o0 = { d[i][j][0] + bi.x, d[i][j][1] + bi.y };
            float2 o1 = { d[i][j][2] + bi.x, d[i][j][3] + bi.y };
            *(float2*)(out + (size_t)r0 * CC + c)       = o0;
            *(float2*)(out + (size_t)(r0 + 8) * CC + c) = o1;
        }
    }
}

// ---------------------------------------------------------------------------
// sim GEMM: sim[b,m,n] = sum_c k[b,m,c]*q[n,b,c];  Kx = exp((sim-1)/eps)
// ---------------------------------------------------------------------------
__global__ __launch_bounds__(256) void gemm_sim_tc(
    const float* __restrict__ kb, const float* __restrict__ qb,
    float* __restrict__ sim, float* __restrict__ Kx)
{
    __shared__ __nv_bfloat16 Ah[128 * AP], Al[128 * AP];
    __shared__ __nv_bfloat16 Bh[64 * AP],  Bl[64 * AP];
    const int b = blockIdx.z;
    const int tid = threadIdx.x;
    const int m0 = blockIdx.y * 128, n0 = blockIdx.x * 64;
    const int lane = tid & 31, warp = tid >> 5;
    const int wm = (warp & 3) * 32, wn = (warp >> 2) * 32;

    float d[2][4][4];
#pragma unroll
    for (int i = 0; i < 2; i++)
#pragma unroll
        for (int j = 0; j < 4; j++)
#pragma unroll
            for (int e = 0; e < 4; e++) d[i][j][e] = 0.f;

    const int ar = tid >> 1, ak = (tid & 1) * 16;
    const int br = tid >> 2, bk = (tid & 3) * 8;
    const float* Ap = kb + ((size_t)b * MM + m0 + ar) * CC + ak;
    const float* Bp = qb + (size_t)(n0 + br) * (BB * CC) + (size_t)b * CC + bk;

    for (int k0 = 0; k0 < CC; k0 += 32) {
#pragma unroll
        for (int i = 0; i < 4; i++)
            store4(Ah, Al, ar * AP + ak + i * 4, *(const float4*)(Ap + k0 + i * 4));
#pragma unroll
        for (int i = 0; i < 2; i++)
            store4(Bh, Bl, br * AP + bk + i * 4, *(const float4*)(Bp + k0 + i * 4));
        __syncthreads();
        mma_phase_nt(Ah, Al, Bh, Bl, wm, wn, lane, d);
        __syncthreads();
    }

#pragma unroll
    for (int i = 0; i < 2; i++) {
        int m = m0 + wm + i * 16 + (lane >> 2);
#pragma unroll
        for (int j = 0; j < 4; j++) {
            int n = n0 + wn + j * 8 + (lane & 3) * 2;
            size_t o0 = ((size_t)b * MM + m) * NQ + n;
            size_t o1 = ((size_t)b * MM + m + 8) * NQ + n;
            float2 s0 = { d[i][j][0], d[i][j][1] };
            float2 s1 = { d[i][j][2], d[i][j][3] };
            *(float2*)(sim + o0) = s0;
            *(float2*)(sim + o1) = s1;
            float2 k0v = { expf((s0.x - 1.0f) / EPS_OT), expf((s0.y - 1.0f) / EPS_OT) };
            float2 k1v = { expf((s1.x - 1.0f) / EPS_OT), expf((s1.y - 1.0f) / EPS_OT) };
            *(float2*)(Kx + o0) = k0v;
            *(float2*)(Kx + o1) = k1v;
        }
    }
}

// ---------------------------------------------------------------------------
// x GEMM: x[n,b,c] = b[n] * sum_m (a[m]*Kx[b,m,n]) * v[b,m,c]
// ---------------------------------------------------------------------------
__global__ __launch_bounds__(256) void gemm_x_tc(
    const float* __restrict__ Kx, const float* __restrict__ v,
    const float* __restrict__ a, const float* __restrict__ bvec,
    float* __restrict__ x)
{
    __shared__ __nv_bfloat16 Ah[32 * XAP], Al[32 * XAP];   // [m][n] natural
    __shared__ __nv_bfloat16 Bh[32 * XBP], Bl[32 * XBP];   // [m][c] natural
    const int b = blockIdx.z;
    const int tid = threadIdx.x;
    const int n0 = blockIdx.y * 128, c0 = blockIdx.x * 64;
    const int lane = tid & 31, warp = tid >> 5;
    const int wm = (warp & 3) * 32, wn = (warp >> 2) * 32;

    float d[2][4][4];
#pragma unroll
    for (int i = 0; i < 2; i++)
#pragma unroll
        for (int j = 0; j < 4; j++)
#pragma unroll
            for (int e = 0; e < 4; e++) d[i][j][e] = 0.f;

    const int amm = tid >> 3, ann = (tid & 7) * 16;   // A: 32 m-rows x 128 n
    const int bmm = tid >> 3, bcc = (tid & 7) * 8;    // B: 32 m-rows x 64 c

    for (int m0k = 0; m0k < MM; m0k += 32) {
        float am = a[b * MM + m0k + amm];
        const float* Ap = Kx + ((size_t)b * MM + m0k + amm) * NQ + n0 + ann;
        const float* Bp = v  + ((size_t)b * MM + m0k + bmm) * CC + c0 + bcc;
#pragma unroll
        for (int i = 0; i < 4; i++) {
            float4 vv = *(const float4*)(Ap + i * 4);
            vv.x *= am; vv.y *= am; vv.z *= am; vv.w *= am;
            store4(Ah, Al, amm * XAP + ann + i * 4, vv);
        }
#pragma unroll
        for (int i = 0; i < 2; i++)
            store4(Bh, Bl, bmm * XBP + bcc + i * 4, *(const float4*)(Bp + i * 4));
        __syncthreads();

#pragma unroll
        for (int ks = 0; ks < 32; ks += 16) {
            uint32_t ah[2][4], al[2][4], bh[4][2], bl[4][2];
#pragma unroll
            for (int i = 0; i < 2; i++) {
                int row = ks + (lane & 7) + ((lane >> 4) << 3);
                int col = wm + i * 16 + ((lane >> 3) & 1) * 8;
                uint32_t off = (uint32_t)(row * XAP + col) * 2;
                ldsm4t(ah[i], s2u(Ah) + off);
                ldsm4t(al[i], s2u(Al) + off);
            }
#pragma unroll
            for (int j = 0; j < 4; j++) {
                int row = ks + (lane & 15);
                int col = wn + j * 8;
                uint32_t off = (uint32_t)(row * XBP + col) * 2;
                ldsm2t(bh[j], s2u(Bh) + off);
                ldsm2t(bl[j], s2u(Bl) + off);
            }
#pragma unroll
            for (int i = 0; i < 2; i++)
#pragma unroll
                for (int j = 0; j < 4; j++) {
                    mma16816(d[i][j], ah[i], bh[j]);
                    mma16816(d[i][j], ah[i], bl[j]);
                    mma16816(d[i][j], al[i], bh[j]);
                }
        }
        __syncthreads();
    }

#pragma unroll
    for (int i = 0; i < 2; i++) {
        int n = n0 + wm + i * 16 + (lane >> 2);
        float bn0 = bvec[b * NQ + n];
        float bn1 = bvec[b * NQ + n + 8];
#pragma unroll
        for (int j = 0; j < 4; j++) {
            int c = c0 + wn + j * 8 + (lane & 3) * 2;
            float2 o0 = { d[i][j][0] * bn0, d[i][j][1] * bn0 };
            float2 o1 = { d[i][j][2] * bn1, d[i][j][3] * bn1 };
            *(float2*)(x + ((size_t)n * BB + b) * CC + c)       = o0;
            *(float2*)(x + ((size_t)(n + 8) * BB + b) * CC + c) = o1;
        }
    }
}

// ---------------------------------------------------------------------------
// l2norm over each 640-element row, in place. One warp per row.
// ---------------------------------------------------------------------------
__global__ __launch_bounds__(256) void l2norm_rows(float* __restrict__ buf)
{
    const int row  = blockIdx.x * 8 + (threadIdx.x >> 5);
    const int lane = threadIdx.x & 31;
    float4* p = (float4*)(buf + (size_t)row * CC);
    float4 vals[5];
    float ss = 0.f;
#pragma unroll
    for (int i = 0; i < 5; i++) {
        vals[i] = p[lane + i * 32];
        ss += vals[i].x*vals[i].x + vals[i].y*vals[i].y
            + vals[i].z*vals[i].z + vals[i].w*vals[i].w;
    }
#pragma unroll
    for (int o = 16; o; o >>= 1) ss += __shfl_xor_sync(0xffffffffu, ss, o);
    float inv = 1.0f / fmaxf(sqrtf(ss), 1e-12f);
#pragma unroll
    for (int i = 0; i < 5; i++) {
        float4 v = vals[i];
        v.x *= inv; v.y *= inv; v.z *= inv; v.w *= inv;
        p[lane + i * 32] = v;
    }
}

// ---------------------------------------------------------------------------
// Sinkhorn prep (mask = int32); also zeroes a (masked rows stay 0 forever).
// ---------------------------------------------------------------------------
__global__ __launch_bounds__(1024) void prep(
    const int* __restrict__ mask,
    float* __restrict__ muP,
    float* __restrict__ bvec,
    float* __restrict__ a)
{
    const int b = blockIdx.x;
    const int m = threadIdx.x;
    int v = (mask[b * MM + m] != 0) ? 1 : 0;
    __shared__ int red[32];
    __shared__ int total;
    int s = v;
#pragma unroll
    for (int o = 16; o; o >>= 1) s += __shfl_xor_sync(0xffffffffu, s, o);
    if ((m & 31) == 0) red[m >> 5] = s;
    __syncthreads();
    if (m < 32) {
        int t = red[m];
#pragma unroll
        for (int o = 16; o; o >>= 1) t += __shfl_xor_sync(0xffffffffu, t, o);
        if (m == 0) total = t;
    }
    __syncthreads();
    int cnt = total;
    muP[b * MM + m]  = v ? (1.0f / (float)cnt + 1e-8f) : 0.0f;
    bvec[b * MM + m] = 1.0f;
    a[b * MM + m]    = 0.0f;
}

// ---------------------------------------------------------------------------
// Fused Sinkhorn iteration (single pass over K):
//   per live row m: s = <K_m, b>; a[m] = mu[m]/s; colpart += a[m]*K_m
// Block = 32 rows of one batch (grid 256 = 8 batches x 32). Row data is
// reused from registers for the colsum accumulation -> K read ONCE per iter.
// Per-block partial colsums written to g_part[blk][0..1023] (deterministic).
// ---------------------------------------------------------------------------
__global__ __launch_bounds__(256) void sink_fused(
    const float* __restrict__ Kx,
    const float* __restrict__ muP,
    const float* __restrict__ bvec,
    float* __restrict__ a,
    float* __restrict__ part)
{
    __shared__ float bs[NQ];
    __shared__ float wpart[8][NQ];
    const int blk  = blockIdx.x;
    const int b    = blk >> 5;
    const int sub  = blk & 31;
    const int tid  = threadIdx.x;
    const int warp = tid >> 5, lane = tid & 31;

    ((float4*)bs)[tid] = ((const float4*)(bvec + b * NQ))[tid];
    __syncthreads();

    float4 acc[8];
#pragma unroll
    for (int i = 0; i < 8; i++) acc[i] = make_float4(0.f, 0.f, 0.f, 0.f);

#pragma unroll
    for (int rr = 0; rr < 4; rr++) {
        const int m = sub * 32 + warp * 4 + rr;
        const float mu = muP[b * MM + m];
        if (mu != 0.f) {
            const float4* row = (const float4*)(Kx + ((size_t)b * MM + m) * NQ);
            float4 kv[8];
            float s = 0.f;
#pragma unroll
            for (int i = 0; i < 8; i++) {
                kv[i] = row[lane + i * 32];
                float4 bv = ((const float4*)bs)[lane + i * 32];
                s += kv[i].x*bv.x + kv[i].y*bv.y + kv[i].z*bv.z + kv[i].w*bv.w;
            }
#pragma unroll
            for (int o = 16; o; o >>= 1) s += __shfl_xor_sync(0xffffffffu, s, o);
            const float av = mu / s;
            if (lane == 0) a[b * MM + m] = av;
#pragma unroll
            for (int i = 0; i < 8; i++) {
                acc[i].x += av * kv[i].x;
                acc[i].y += av * kv[i].y;
                acc[i].z += av * kv[i].z;
                acc[i].w += av * kv[i].w;
            }
        }
    }

#pragma unroll
    for (int i = 0; i < 8; i++)
        ((float4*)wpart[warp])[lane + i * 32] = acc[i];
    __syncthreads();

    // reduce 8 warps -> per-block partial, write to g_part[blk]
    {
        float4 t = ((const float4*)wpart[0])[tid];
#pragma unroll
        for (int w = 1; w < 8; w++) {
            float4 u = ((const float4*)wpart[w])[tid];
            t.x += u.x; t.y += u.y; t.z += u.z; t.w += u.w;
        }
        ((float4*)(part + (size_t)blk * NQ))[tid] = t;
    }
}

// ---------------------------------------------------------------------------
// Finalize iteration: b[b,n] = nuP / sum_{sub} part[b*32+sub][n]
// grid 32 (= 8 batches x 4 col-quarters), 256 threads: one col per thread.
// ---------------------------------------------------------------------------
__global__ __launch_bounds__(256) void sink_finalize(
    const float* __restrict__ part,
    float* __restrict__ bvec)
{
    const int b   = blockIdx.x >> 2;
    const int col = (blockIdx.x & 3) * 256 + threadIdx.x;
    const float nuP = 1.0f / (float)NQ + 1e-8f;
    const float* p = part + (size_t)(b * 32) * NQ + col;
    float t = 0.f;
#pragma unroll
    for (int s = 0; s < 32; s++) t += p[(size_t)s * NQ];
    bvec[b * NQ + col] = (t > 0.f) ? (nuP / t) : 0.f;
}

// ---------------------------------------------------------------------------
// attn_save[b,m] = mask ? M*Nq * a[m] * sum_n sim*Kx*b[n] : 0
// ---------------------------------------------------------------------------
__global__ __launch_bounds__(256) void attn_kernel(
    const float* __restrict__ sim,
    const float* __restrict__ Kx,
    const float* __restrict__ a,
    const float* __restrict__ bvec,
    const float* __restrict__ muP,
    float* __restrict__ out_attn)
{
    __shared__ float bs[NQ];
    const int blk = blockIdx.x;
    const int b   = blk >> 7;
    const int m   = (blk & 127) * 8 + (threadIdx.x >> 5);
    const int lane = threadIdx.x & 31;
    ((float4*)bs)[threadIdx.x] = ((const float4*)(bvec + b * NQ))[threadIdx.x];
    __syncthreads();
    float mu  = muP[b * MM + m];
    float val = 0.f;
    if (mu != 0.f) {
        size_t off = ((size_t)b * MM + m) * NQ;
        const float4* srow = (const float4*)(sim + off);
        const float4* krow = (const float4*)(Kx + off);
        float s = 0.f;
#pragma unroll
        for (int i = 0; i < 8; i++) {
            float4 sv = srow[lane + i * 32];
            float4 kv = krow[lane + i * 32];
            float4 bv = ((const float4*)bs)[lane + i * 32];
            s += sv.x*kv.x*bv.x + sv.y*kv.y*bv.y + sv.z*kv.z*bv.z + sv.w*kv.w*bv.w;
        }
#pragma unroll
        for (int o = 16; o; o >>= 1) s += __shfl_xor_sync(0xffffffffu, s, o);
        val = (float)(MM) * (float)(NQ) * a[b * MM + m] * s;
    }
    if (lane == 0) out_attn[b * MM + m] = val;
}

// ---------------------------------------------------------------------------
extern "C" void kernel_launch(void* const* d_in, const int* in_sizes, int n_in,
                              void* d_out, int out_size)
{
    const float* xq = (const float*)d_in[0];
    const float* xk = (const float*)d_in[1];
    const float* xv = (const float*)d_in[2];
    const int*   mask = (const int*)d_in[3];
    const float* Wq = (const float*)d_in[4];
    const float* bq = (const float*)d_in[5];
    const float* Wk = (const float*)d_in[6];
    const float* bk = (const float*)d_in[7];
    const float* Wv = (const float*)d_in[8];
    const float* bv = (const float*)d_in[9];
    const float* Wp = (const float*)d_in[10];
    const float* bp = (const float*)d_in[11];

    float* out  = (float*)d_out;
    float* attn = out + (size_t)RR * CC;

    float *q, *k, *v, *x, *sim, *Kx, *a, *b, *mu, *part;
    cudaGetSymbolAddress((void**)&q,    g_q);
    cudaGetSymbolAddress((void**)&k,    g_k);
    cudaGetSymbolAddress((void**)&v,    g_v);
    cudaGetSymbolAddress((void**)&x,    g_x);
    cudaGetSymbolAddress((void**)&sim,  g_sim);
    cudaGetSymbolAddress((void**)&Kx,   g_Kx);
    cudaGetSymbolAddress((void**)&a,    g_a);
    cudaGetSymbolAddress((void**)&b,    g_b);
    cudaGetSymbolAddress((void**)&mu,   g_mu);
    cudaGetSymbolAddress((void**)&part, g_part);

    dim3 gP(CC / 64, RR / 128);   // (10, 64)

    gemm_proj_tc<<<gP, 256>>>(xq, Wq, bq, q);
    gemm_proj_tc<<<gP, 256>>>(xk, Wk, bk, k);
    gemm_proj_tc<<<gP, 256>>>(xv, Wv, bv, v);
    l2norm_rows<<<RR / 8, 256>>>(q);
    l2norm_rows<<<RR / 8, 256>>>(k);
    prep<<<BB, 1024>>>(mask, mu, b, a);

    gemm_sim_tc<<<dim3(NQ / 64, MM / 128, BB), 256>>>(k, q, sim, Kx);

    for (int it = 0; it < N_ITERS; it++) {
        sink_fused<<<256, 256>>>(Kx, mu, b, a, part);
        sink_finalize<<<32, 256>>>(part, b);
    }

    attn_kernel<<<(BB * MM) / 8, 256>>>(sim, Kx, a, b, mu, attn);
    gemm_x_tc<<<dim3(CC / 64, NQ / 128, BB), 256>>>(Kx, v, a, b, x);
    gemm_proj_tc<<<gP, 256>>>(x, Wp, bp, out);
}

// round 15
// speedup vs baseline: 2.4278x; 1.0093x over previous
#include <cuda_runtime.h>
#include <cuda_bf16.h>
#include <math.h>
#include <stdint.h>

// ---------------------------------------------------------------------------
//   xq: (1024, 8, 640)   xk/xv: (8, 1024, 640)   mask: (8, 1024) int32 (bool)
//   Wq/Wk/Wv/Wp: (640,640), biases (640)
//   out: (1024, 8, 640) fp32, attn_save: (8, 1024) fp32
// ---------------------------------------------------------------------------
#define NQ   1024
#define BB   8
#define MM   1024
#define CC   640
#define RR   (NQ * BB)
#define EPS_OT 0.05f
#define N_ITERS 100

#define AP   40     // smem pitch (bf16) for NT tiles, K-tile 32 + 8 pad
#define XAP  136    // gemm_x A tile pitch: n=128 + 8
#define XBP  72     // gemm_x B tile pitch: c=64 + 8

// ---------------- static device scratch (allocation-free rule) -------------
__device__ float g_q  [RR * CC];
__device__ float g_k  [RR * CC];
__device__ float g_v  [RR * CC];
__device__ float g_x  [RR * CC];
__device__ float g_sim[(size_t)BB * MM * NQ];
__device__ float g_Kx [(size_t)BB * MM * NQ];
__device__ float g_a  [BB * MM];
__device__ float g_b  [BB * NQ];
__device__ float g_mu [BB * MM];
__device__ float g_part[256 * NQ];   // per-block partial colsums (1 MB)

// ---------------------------------------------------------------------------
// MMA / ldmatrix helpers
// ---------------------------------------------------------------------------
__device__ __forceinline__ uint32_t s2u(const void* p) {
    return (uint32_t)__cvta_generic_to_shared(p);
}
__device__ __forceinline__ void mma16816(float* d, const uint32_t* a, const uint32_t* b) {
    asm volatile(
        "mma.sync.aligned.m16n8k16.row.col.f32.bf16.bf16.f32 "
        "{%0,%1,%2,%3}, {%4,%5,%6,%7}, {%8,%9}, {%0,%1,%2,%3};\n"
        : "+f"(d[0]), "+f"(d[1]), "+f"(d[2]), "+f"(d[3])
        : "r"(a[0]), "r"(a[1]), "r"(a[2]), "r"(a[3]), "r"(b[0]), "r"(b[1]));
}
__device__ __forceinline__ void ldsm4(uint32_t* r, uint32_t a) {
    asm volatile("ldmatrix.sync.aligned.m8n8.x4.shared.b16 {%0,%1,%2,%3}, [%4];\n"
                 : "=r"(r[0]), "=r"(r[1]), "=r"(r[2]), "=r"(r[3]) : "r"(a));
}
__device__ __forceinline__ void ldsm4t(uint32_t* r, uint32_t a) {
    asm volatile("ldmatrix.sync.aligned.m8n8.x4.trans.shared.b16 {%0,%1,%2,%3}, [%4];\n"
                 : "=r"(r[0]), "=r"(r[1]), "=r"(r[2]), "=r"(r[3]) : "r"(a));
}
// fp32 -> bf16 hi + residual lo (hi+lo carries 16 mantissa bits; products exact)
__device__ __forceinline__ void split2(float f, __nv_bfloat16& h, __nv_bfloat16& l) {
    h = __float2bfloat16(f);
    l = __float2bfloat16(f - __bfloat162float(h));
}
__device__ __forceinline__ void store4(__nv_bfloat16* H, __nv_bfloat16* L, int base, float4 v) {
    __nv_bfloat16 h0,l0,h1,l1,h2,l2,h3,l3;
    split2(v.x,h0,l0); split2(v.y,h1,l1); split2(v.z,h2,l2); split2(v.w,h3,l3);
    __nv_bfloat162 a; a.x=h0; a.y=h1; __nv_bfloat162 b; b.x=h2; b.y=h3;
    __nv_bfloat162 c; c.x=l0; c.y=l1; __nv_bfloat162 d; d.x=l2; d.y=l3;
    *(__nv_bfloat162*)(H + base)     = a;
    *(__nv_bfloat162*)(H + base + 2) = b;
    *(__nv_bfloat162*)(L + base)     = c;
    *(__nv_bfloat162*)(L + base + 2) = d;
}

// NT mma phase over one BK=32 smem tile: A[128][32] x B[64][32] -> d[2][4][4]
// B fragments fetched pairwise via ldsm.x4 (j and j+1 in one instruction).
__device__ __forceinline__ void mma_phase_nt(
    const __nv_bfloat16* Ah, const __nv_bfloat16* Al,
    const __nv_bfloat16* Bh, const __nv_bfloat16* Bl,
    int wm, int wn, int lane, float d[2][4][4])
{
#pragma unroll
    for (int ks = 0; ks < 32; ks += 16) {
        uint32_t ah[2][4], al[2][4], bh[4][2], bl[4][2];
#pragma unroll
        for (int i = 0; i < 2; i++) {
            int row = wm + i * 16 + (lane & 15);
            int col = ks + (lane >> 4) * 8;
            uint32_t off = (uint32_t)(row * AP + col) * 2;
            ldsm4(ah[i], s2u(Ah) + off);
            ldsm4(al[i], s2u(Al) + off);
        }
#pragma unroll
        for (int jp = 0; jp < 2; jp++) {
            int g = lane >> 3;
            int row = wn + jp * 16 + (g >> 1) * 8 + (lane & 7);
            int col = ks + (g & 1) * 8;
            uint32_t off = (uint32_t)(row * AP + col) * 2;
            uint32_t t[4];
            ldsm4(t, s2u(Bh) + off);
            bh[2*jp][0] = t[0]; bh[2*jp][1] = t[1];
            bh[2*jp+1][0] = t[2]; bh[2*jp+1][1] = t[3];
            ldsm4(t, s2u(Bl) + off);
            bl[2*jp][0] = t[0]; bl[2*jp][1] = t[1];
            bl[2*jp+1][0] = t[2]; bl[2*jp+1][1] = t[3];
        }
#pragma unroll
        for (int i = 0; i < 2; i++)
#pragma unroll
            for (int j = 0; j < 4; j++) {
                mma16816(d[i][j], ah[i], bh[j]);
                mma16816(d[i][j], ah[i], bl[j]);
                mma16816(d[i][j], al[i], bh[j]);
            }
    }
}

// ---------------------------------------------------------------------------
// Projection GEMM via tensor cores (register-prefetch pipelined):
// out[r,j] = sum_c A[r,c] * W[j,c] + bias[j]    (M=8192, N=640, K=640)
// ---------------------------------------------------------------------------
__global__ __launch_bounds__(256, 2) void gemm_proj_tc(
    const float* __restrict__ A, const float* __restrict__ W,
    const float* __restrict__ bias, float* __restrict__ out)
{
    __shared__ __nv_bfloat16 Ah[128 * AP], Al[128 * AP];
    __shared__ __nv_bfloat16 Bh[64 * AP],  Bl[64 * AP];
    const int tid = threadIdx.x;
    const int m0 = blockIdx.y * 128, n0 = blockIdx.x * 64;
    const int lane = tid & 31, warp = tid >> 5;
    const int wm = (warp & 3) * 32, wn = (warp >> 2) * 32;

    float d[2][4][4];
#pragma unroll
    for (int i = 0; i < 2; i++)
#pragma unroll
        for (int j = 0; j < 4; j++)
#pragma unroll
            for (int e = 0; e < 4; e++) d[i][j][e] = 0.f;

    const int ar = tid >> 1, ak = (tid & 1) * 16;
    const int br = tid >> 2, bk = (tid & 3) * 8;
    const float* Ap = A + (size_t)(m0 + ar) * CC + ak;
    const float* Bp = W + (size_t)(n0 + br) * CC + bk;

    float4 aS[4], bS[2];
#pragma unroll
    for (int i = 0; i < 4; i++) aS[i] = *(const float4*)(Ap + i * 4);
#pragma unroll
    for (int i = 0; i < 2; i++) bS[i] = *(const float4*)(Bp + i * 4);

    for (int k0 = 0; k0 < CC; k0 += 32) {
#pragma unroll
        for (int i = 0; i < 4; i++)
            store4(Ah, Al, ar * AP + ak + i * 4, aS[i]);
#pragma unroll
        for (int i = 0; i < 2; i++)
            store4(Bh, Bl, br * AP + bk + i * 4, bS[i]);
        __syncthreads();
        if (k0 + 32 < CC) {
#pragma unroll
            for (int i = 0; i < 4; i++) aS[i] = *(const float4*)(Ap + k0 + 32 + i * 4);
#pragma unroll
            for (int i = 0; i < 2; i++) bS[i] = *(const float4*)(Bp + k0 + 32 + i * 4);
        }
        mma_phase_nt(Ah, Al, Bh, Bl, wm, wn, lane, d);
        __syncthreads();
    }

#pragma unroll
    for (int i = 0; i < 2; i++) {
        int r0 = m0 + wm + i * 16 + (lane >> 2);
#pragma unroll
        for (int j = 0; j < 4; j++) {
            int c = n0 + wn + j * 8 + (lane & 3) * 2;
            float2 bi = *(const float2*)(bias + c);
            float2 o0 = { d[i][j][0] + bi.x, d[i][j][1] + bi.y };
            float2 o1 = { d[i][j][2] + bi.x, d[i][j][3] + bi.y };
            *(float2*)(out + (size_t)r0 * CC + c)       = o0;
            *(float2*)(out + (size_t)(r0 + 8) * CC + c) = o1;
        }
    }
}

// ---------------------------------------------------------------------------
// sim GEMM: sim[b,m,n] = sum_c k[b,m,c]*q[n,b,c];  Kx = exp((sim-1)/eps)
// ---------------------------------------------------------------------------
__global__ __launch_bounds__(256, 2) void gemm_sim_tc(
    const float* __restrict__ kb, const float* __restrict__ qb,
    float* __restrict__ sim, float* __restrict__ Kx)
{
    __shared__ __nv_bfloat16 Ah[128 * AP], Al[128 * AP];
    __shared__ __nv_bfloat16 Bh[64 * AP],  Bl[64 * AP];
    const int b = blockIdx.z;
    const int tid = threadIdx.x;
    const int m0 = blockIdx.y * 128, n0 = blockIdx.x * 64;
    const int lane = tid & 31, warp = tid >> 5;
    const int wm = (warp & 3) * 32, wn = (warp >> 2) * 32;

    float d[2][4][4];
#pragma unroll
    for (int i = 0; i < 2; i++)
#pragma unroll
        for (int j = 0; j < 4; j++)
#pragma unroll
            for (int e = 0; e < 4; e++) d[i][j][e] = 0.f;

    const int ar = tid >> 1, ak = (tid & 1) * 16;
    const int br = tid >> 2, bk = (tid & 3) * 8;
    const float* Ap = kb + ((size_t)b * MM + m0 + ar) * CC + ak;
    const float* Bp = qb + (size_t)(n0 + br) * (BB * CC) + (size_t)b * CC + bk;

    float4 aS[4], bS[2];
#pragma unroll
    for (int i = 0; i < 4; i++) aS[i] = *(const float4*)(Ap + i * 4);
#pragma unroll
    for (int i = 0; i < 2; i++) bS[i] = *(const float4*)(Bp + i * 4);

    for (int k0 = 0; k0 < CC; k0 += 32) {
#pragma unroll
        for (int i = 0; i < 4; i++)
            store4(Ah, Al, ar * AP + ak + i * 4, aS[i]);
#pragma unroll
        for (int i = 0; i < 2; i++)
            store4(Bh, Bl, br * AP + bk + i * 4, bS[i]);
        __syncthreads();
        if (k0 + 32 < CC) {
#pragma unroll
            for (int i = 0; i < 4; i++) aS[i] = *(const float4*)(Ap + k0 + 32 + i * 4);
#pragma unroll
            for (int i = 0; i < 2; i++) bS[i] = *(const float4*)(Bp + k0 + 32 + i * 4);
        }
        mma_phase_nt(Ah, Al, Bh, Bl, wm, wn, lane, d);
        __syncthreads();
    }

#pragma unroll
    for (int i = 0; i < 2; i++) {
        int m = m0 + wm + i * 16 + (lane >> 2);
#pragma unroll
        for (int j = 0; j < 4; j++) {
            int n = n0 + wn + j * 8 + (lane & 3) * 2;
            size_t o0 = ((size_t)b * MM + m) * NQ + n;
            size_t o1 = ((size_t)b * MM + m + 8) * NQ + n;
            float2 s0 = { d[i][j][0], d[i][j][1] };
            float2 s1 = { d[i][j][2], d[i][j][3] };
            *(float2*)(sim + o0) = s0;
            *(float2*)(sim + o1) = s1;
            float2 k0v = { expf((s0.x - 1.0f) / EPS_OT), expf((s0.y - 1.0f) / EPS_OT) };
            float2 k1v = { expf((s1.x - 1.0f) / EPS_OT), expf((s1.y - 1.0f) / EPS_OT) };
            *(float2*)(Kx + o0) = k0v;
            *(float2*)(Kx + o1) = k1v;
        }
    }
}

// ---------------------------------------------------------------------------
// x GEMM: x[n,b,c] = b[n] * sum_m (a[m]*Kx[b,m,n]) * v[b,m,c]
// ---------------------------------------------------------------------------
__global__ __launch_bounds__(256, 2) void gemm_x_tc(
    const float* __restrict__ Kx, const float* __restrict__ v,
    const float* __restrict__ a, const float* __restrict__ bvec,
    float* __restrict__ x)
{
    __shared__ __nv_bfloat16 Ah[32 * XAP], Al[32 * XAP];   // [m][n] natural
    __shared__ __nv_bfloat16 Bh[32 * XBP], Bl[32 * XBP];   // [m][c] natural
    const int b = blockIdx.z;
    const int tid = threadIdx.x;
    const int n0 = blockIdx.y * 128, c0 = blockIdx.x * 64;
    const int lane = tid & 31, warp = tid >> 5;
    const int wm = (warp & 3) * 32, wn = (warp >> 2) * 32;

    float d[2][4][4];
#pragma unroll
    for (int i = 0; i < 2; i++)
#pragma unroll
        for (int j = 0; j < 4; j++)
#pragma unroll
            for (int e = 0; e < 4; e++) d[i][j][e] = 0.f;

    const int amm = tid >> 3, ann = (tid & 7) * 16;   // A: 32 m-rows x 128 n
    const int bmm = tid >> 3, bcc = (tid & 7) * 8;    // B: 32 m-rows x 64 c

    float4 aS[4], bS[2];
    float amS = a[b * MM + amm];
    {
        const float* Ap0 = Kx + ((size_t)b * MM + amm) * NQ + n0 + ann;
        const float* Bp0 = v  + ((size_t)b * MM + bmm) * CC + c0 + bcc;
#pragma unroll
        for (int i = 0; i < 4; i++) aS[i] = *(const float4*)(Ap0 + i * 4);
#pragma unroll
        for (int i = 0; i < 2; i++) bS[i] = *(const float4*)(Bp0 + i * 4);
    }

    for (int m0k = 0; m0k < MM; m0k += 32) {
        const float am = amS;
#pragma unroll
        for (int i = 0; i < 4; i++) {
            float4 vv = aS[i];
            vv.x *= am; vv.y *= am; vv.z *= am; vv.w *= am;
            store4(Ah, Al, amm * XAP + ann + i * 4, vv);
        }
#pragma unroll
        for (int i = 0; i < 2; i++)
            store4(Bh, Bl, bmm * XBP + bcc + i * 4, bS[i]);
        __syncthreads();

        if (m0k + 32 < MM) {
            amS = a[b * MM + m0k + 32 + amm];
            const float* Ap = Kx + ((size_t)b * MM + m0k + 32 + amm) * NQ + n0 + ann;
            const float* Bp = v  + ((size_t)b * MM + m0k + 32 + bmm) * CC + c0 + bcc;
#pragma unroll
            for (int i = 0; i < 4; i++) aS[i] = *(const float4*)(Ap + i * 4);
#pragma unroll
            for (int i = 0; i < 2; i++) bS[i] = *(const float4*)(Bp + i * 4);
        }

#pragma unroll
        for (int ks = 0; ks < 32; ks += 16) {
            uint32_t ah[2][4], al[2][4], bh[4][2], bl[4][2];
#pragma unroll
            for (int i = 0; i < 2; i++) {
                int row = ks + (lane & 7) + ((lane >> 4) << 3);
                int col = wm + i * 16 + ((lane >> 3) & 1) * 8;
                uint32_t off = (uint32_t)(row * XAP + col) * 2;
                ldsm4t(ah[i], s2u(Ah) + off);
                ldsm4t(al[i], s2u(Al) + off);
            }
#pragma unroll
            for (int jp = 0; jp < 2; jp++) {
                int g = lane >> 3;
                int row = ks + (g & 1) * 8 + (lane & 7);
                int col = wn + jp * 16 + (g >> 1) * 8;
                uint32_t off = (uint32_t)(row * XBP + col) * 2;
                uint32_t t[4];
                ldsm4t(t, s2u(Bh) + off);
                bh[2*jp][0] = t[0]; bh[2*jp][1] = t[1];
                bh[2*jp+1][0] = t[2]; bh[2*jp+1][1] = t[3];
                ldsm4t(t, s2u(Bl) + off);
                bl[2*jp][0] = t[0]; bl[2*jp][1] = t[1];
                bl[2*jp+1][0] = t[2]; bl[2*jp+1][1] = t[3];
            }
#pragma unroll
            for (int i = 0; i < 2; i++)
#pragma unroll
                for (int j = 0; j < 4; j++) {
                    mma16816(d[i][j], ah[i], bh[j]);
                    mma16816(d[i][j], ah[i], bl[j]);
                    mma16816(d[i][j], al[i], bh[j]);
                }
        }
        __syncthreads();
    }

#pragma unroll
    for (int i = 0; i < 2; i++) {
        int n = n0 + wm + i * 16 + (lane >> 2);
        float bn0 = bvec[b * NQ + n];
        float bn1 = bvec[b * NQ + n + 8];
#pragma unroll
        for (int j = 0; j < 4; j++) {
            int c = c0 + wn + j * 8 + (lane & 3) * 2;
            float2 o0 = { d[i][j][0] * bn0, d[i][j][1] * bn0 };
            float2 o1 = { d[i][j][2] * bn1, d[i][j][3] * bn1 };
            *(float2*)(x + ((size_t)n * BB + b) * CC + c)       = o0;
            *(float2*)(x + ((size_t)(n + 8) * BB + b) * CC + c) = o1;
        }
    }
}

// ---------------------------------------------------------------------------
// l2norm over each 640-element row, in place. One warp per row.
// ---------------------------------------------------------------------------
__global__ __launch_bounds__(256) void l2norm_rows(float* __restrict__ buf)
{
    const int row  = blockIdx.x * 8 + (threadIdx.x >> 5);
    const int lane = threadIdx.x & 31;
    float4* p = (float4*)(buf + (size_t)row * CC);
    float4 vals[5];
    float ss = 0.f;
#pragma unroll
    for (int i = 0; i < 5; i++) {
        vals[i] = p[lane + i * 32];
        ss += vals[i].x*vals[i].x + vals[i].y*vals[i].y
            + vals[i].z*vals[i].z + vals[i].w*vals[i].w;
    }
#pragma unroll
    for (int o = 16; o; o >>= 1) ss += __shfl_xor_sync(0xffffffffu, ss, o);
    float inv = 1.0f / fmaxf(sqrtf(ss), 1e-12f);
#pragma unroll
    for (int i = 0; i < 5; i++) {
        float4 v = vals[i];
        v.x *= inv; v.y *= inv; v.z *= inv; v.w *= inv;
        p[lane + i * 32] = v;
    }
}

// ---------------------------------------------------------------------------
// Sinkhorn prep (mask = int32); also zeroes a (masked rows stay 0 forever).
// ---------------------------------------------------------------------------
__global__ __launch_bounds__(1024) void prep(
    const int* __restrict__ mask,
    float* __restrict__ muP,
    float* __restrict__ bvec,
    float* __restrict__ a)
{
    const int b = blockIdx.x;
    const int m = threadIdx.x;
    int v = (mask[b * MM + m] != 0) ? 1 : 0;
    __shared__ int red[32];
    __shared__ int total;
    int s = v;
#pragma unroll
    for (int o = 16; o; o >>= 1) s += __shfl_xor_sync(0xffffffffu, s, o);
    if ((m & 31) == 0) red[m >> 5] = s;
    __syncthreads();
    if (m < 32) {
        int t = red[m];
#pragma unroll
        for (int o = 16; o; o >>= 1) t += __shfl_xor_sync(0xffffffffu, t, o);
        if (m == 0) total = t;
    }
    __syncthreads();
    int cnt = total;
    muP[b * MM + m]  = v ? (1.0f / (float)cnt + 1e-8f) : 0.0f;
    bvec[b * MM + m] = 1.0f;
    a[b * MM + m]    = 0.0f;
}

// ---------------------------------------------------------------------------
// Fused Sinkhorn iteration (single pass over K):
//   per live row m: s = <K_m, b>; a[m] = mu[m]/s; colpart += a[m]*K_m
// Block = 32 rows of one batch (grid 256 = 8 batches x 32). Row data is
// reused from registers for the colsum accumulation -> K read ONCE per iter.
// ---------------------------------------------------------------------------
__global__ __launch_bounds__(256) void sink_fused(
    const float* __restrict__ Kx,
    const float* __restrict__ muP,
    const float* __restrict__ bvec,
    float* __restrict__ a,
    float* __restrict__ part)
{
    __shared__ float bs[NQ];
    __shared__ float wpart[8][NQ];
    const int blk  = blockIdx.x;
    const int b    = blk >> 5;
    const int sub  = blk & 31;
    const int tid  = threadIdx.x;
    const int warp = tid >> 5, lane = tid & 31;

    ((float4*)bs)[tid] = ((const float4*)(bvec + b * NQ))[tid];
    __syncthreads();

    float4 acc[8];
#pragma unroll
    for (int i = 0; i < 8; i++) acc[i] = make_float4(0.f, 0.f, 0.f, 0.f);

#pragma unroll
    for (int rr = 0; rr < 4; rr++) {
        const int m = sub * 32 + warp * 4 + rr;
        const float mu = muP[b * MM + m];
        if (mu != 0.f) {
            const float4* row = (const float4*)(Kx + ((size_t)b * MM + m) * NQ);
            float4 kv[8];
            float s = 0.f;
#pragma unroll
            for (int i = 0; i < 8; i++) {
                kv[i] = row[lane + i * 32];
                float4 bv = ((const float4*)bs)[lane + i * 32];
                s += kv[i].x*bv.x + kv[i].y*bv.y + kv[i].z*bv.z + kv[i].w*bv.w;
            }
#pragma unroll
            for (int o = 16; o; o >>= 1) s += __shfl_xor_sync(0xffffffffu, s, o);
            const float av = mu / s;
            if (lane == 0) a[b * MM + m] = av;
#pragma unroll
            for (int i = 0; i < 8; i++) {
                acc[i].x += av * kv[i].x;
                acc[i].y += av * kv[i].y;
                acc[i].z += av * kv[i].z;
                acc[i].w += av * kv[i].w;
            }
        }
    }

#pragma unroll
    for (int i = 0; i < 8; i++)
        ((float4*)wpart[warp])[lane + i * 32] = acc[i];
    __syncthreads();

    {
        float4 t = ((const float4*)wpart[0])[tid];
#pragma unroll
        for (int w = 1; w < 8; w++) {
            float4 u = ((const float4*)wpart[w])[tid];
            t.x += u.x; t.y += u.y; t.z += u.z; t.w += u.w;
        }
        ((float4*)(part + (size_t)blk * NQ))[tid] = t;
    }
}

// ---------------------------------------------------------------------------
// Finalize iteration: b[b,n] = nuP / sum_{sub} part[b*32+sub][n]
// ---------------------------------------------------------------------------
__global__ __launch_bounds__(256) void sink_finalize(
    const float* __restrict__ part,
    float* __restrict__ bvec)
{
    const int b   = blockIdx.x >> 2;
    const int col = (blockIdx.x & 3) * 256 + threadIdx.x;
    const float nuP = 1.0f / (float)NQ + 1e-8f;
    const float* p = part + (size_t)(b * 32) * NQ + col;
    float t = 0.f;
#pragma unroll
    for (int s = 0; s < 32; s++) t += p[(size_t)s * NQ];
    bvec[b * NQ + col] = (t > 0.f) ? (nuP / t) : 0.f;
}

// ---------------------------------------------------------------------------
// attn_save[b,m] = mask ? M*Nq * a[m] * sum_n sim*Kx*b[n] : 0
// ---------------------------------------------------------------------------
__global__ __launch_bounds__(256) void attn_kernel(
    const float* __restrict__ sim,
    const float* __restrict__ Kx,
    const float* __restrict__ a,
    const float* __restrict__ bvec,
    const float* __restrict__ muP,
    float* __restrict__ out_attn)
{
    __shared__ float bs[NQ];
    const int blk = blockIdx.x;
    const int b   = blk >> 7;
    const int m   = (blk & 127) * 8 + (threadIdx.x >> 5);
    const int lane = threadIdx.x & 31;
    ((float4*)bs)[threadIdx.x] = ((const float4*)(bvec + b * NQ))[threadIdx.x];
    __syncthreads();
    float mu  = muP[b * MM + m];
    float val = 0.f;
    if (mu != 0.f) {
        size_t off = ((size_t)b * MM + m) * NQ;
        const float4* srow = (const float4*)(sim + off);
        const float4* krow = (const float4*)(Kx + off);
        float s = 0.f;
#pragma unroll
        for (int i = 0; i < 8; i++) {
            float4 sv = srow[lane + i * 32];
            float4 kv = krow[lane + i * 32];
            float4 bv = ((const float4*)bs)[lane + i * 32];
            s += sv.x*kv.x*bv.x + sv.y*kv.y*bv.y + sv.z*kv.z*bv.z + sv.w*kv.w*bv.w;
        }
#pragma unroll
        for (int o = 16; o; o >>= 1) s += __shfl_xor_sync(0xffffffffu, s, o);
        val = (float)(MM) * (float)(NQ) * a[b * MM + m] * s;
    }
    if (lane == 0) out_attn[b * MM + m] = val;
}

// ---------------------------------------------------------------------------
extern "C" void kernel_launch(void* const* d_in, const int* in_sizes, int n_in,
                              void* d_out, int out_size)
{
    const float* xq = (const float*)d_in[0];
    const float* xk = (const float*)d_in[1];
    const float* xv = (const float*)d_in[2];
    const int*   mask = (const int*)d_in[3];
    const float* Wq = (const float*)d_in[4];
    const float* bq = (const float*)d_in[5];
    const float* Wk = (const float*)d_in[6];
    const float* bk = (const float*)d_in[7];
    const float* Wv = (const float*)d_in[8];
    const float* bv = (const float*)d_in[9];
    const float* Wp = (const float*)d_in[10];
    const float* bp = (const float*)d_in[11];

    float* out  = (float*)d_out;
    float* attn = out + (size_t)RR * CC;

    float *q, *k, *v, *x, *sim, *Kx, *a, *b, *mu, *part;
    cudaGetSymbolAddress((void**)&q,    g_q);
    cudaGetSymbolAddress((void**)&k,    g_k);
    cudaGetSymbolAddress((void**)&v,    g_v);
    cudaGetSymbolAddress((void**)&x,    g_x);
    cudaGetSymbolAddress((void**)&sim,  g_sim);
    cudaGetSymbolAddress((void**)&Kx,   g_Kx);
    cudaGetSymbolAddress((void**)&a,    g_a);
    cudaGetSymbolAddress((void**)&b,    g_b);
    cudaGetSymbolAddress((void**)&mu,   g_mu);
    cudaGetSymbolAddress((void**)&part, g_part);

    dim3 gP(CC / 64, RR / 128);   // (10, 64)

    gemm_proj_tc<<<gP, 256>>>(xq, Wq, bq, q);
    gemm_proj_tc<<<gP, 256>>>(xk, Wk, bk, k);
    gemm_proj_tc<<<gP, 256>>>(xv, Wv, bv, v);
    l2norm_rows<<<RR / 8, 256>>>(q);
    l2norm_rows<<<RR / 8, 256>>>(k);
    prep<<<BB, 1024>>>(mask, mu, b, a);

    gemm_sim_tc<<<dim3(NQ / 64, MM / 128, BB), 256>>>(k, q, sim, Kx);

    for (int it = 0; it < N_ITERS; it++) {
        sink_fused<<<256, 256>>>(Kx, mu, b, a, part);
        sink_finalize<<<32, 256>>>(part, b);
    }

    attn_kernel<<<(BB * MM) / 8, 256>>>(sim, Kx, a, b, mu, attn);
    gemm_x_tc<<<dim3(CC / 64, NQ / 128, BB), 256>>>(Kx, v, a, b, x);
    gemm_proj_tc<<<gP, 256>>>(x, Wp, bp, out);
}

// round 16
// speedup vs baseline: 2.5595x; 1.0542x over previous
#include <cuda_runtime.h>
#include <cuda_bf16.h>
#include <math.h>
#include <stdint.h>

// ---------------------------------------------------------------------------
//   xq: (1024, 8, 640)   xk/xv: (8, 1024, 640)   mask: (8, 1024) int32 (bool)
//   Wq/Wk/Wv/Wp: (640,640), biases (640)
//   out: (1024, 8, 640) fp32, attn_save: (8, 1024) fp32
// ---------------------------------------------------------------------------
#define NQ   1024
#define BB   8
#define MM   1024
#define CC   640
#define RR   (NQ * BB)
#define EPS_OT 0.05f
#define N_ITERS 100

#define AP   40     // smem pitch (bf16) for NT tiles, K-tile 32 + 8 pad
#define XAP  136    // gemm_x A tile pitch: n=128 + 8
#define XBP  72     // gemm_x B tile pitch: c=64 + 8

#define SPB  16     // sinkhorn partials per batch (128 blocks total)

// ---------------- static device scratch (allocation-free rule) -------------
__device__ float g_q  [RR * CC];
__device__ float g_k  [RR * CC];
__device__ float g_v  [RR * CC];
__device__ float g_x  [RR * CC];
__device__ float g_sim[(size_t)BB * MM * NQ];
__device__ float g_Kx [(size_t)BB * MM * NQ];
__device__ float g_a  [BB * MM];
__device__ float g_b  [BB * NQ];
__device__ float g_mu [BB * MM];
__device__ float g_part[BB * SPB * NQ];   // per-block partial colsums (512 KB)

// ---------------------------------------------------------------------------
// MMA / ldmatrix helpers
// ---------------------------------------------------------------------------
__device__ __forceinline__ uint32_t s2u(const void* p) {
    return (uint32_t)__cvta_generic_to_shared(p);
}
__device__ __forceinline__ void mma16816(float* d, const uint32_t* a, const uint32_t* b) {
    asm volatile(
        "mma.sync.aligned.m16n8k16.row.col.f32.bf16.bf16.f32 "
        "{%0,%1,%2,%3}, {%4,%5,%6,%7}, {%8,%9}, {%0,%1,%2,%3};\n"
        : "+f"(d[0]), "+f"(d[1]), "+f"(d[2]), "+f"(d[3])
        : "r"(a[0]), "r"(a[1]), "r"(a[2]), "r"(a[3]), "r"(b[0]), "r"(b[1]));
}
__device__ __forceinline__ void ldsm4(uint32_t* r, uint32_t a) {
    asm volatile("ldmatrix.sync.aligned.m8n8.x4.shared.b16 {%0,%1,%2,%3}, [%4];\n"
                 : "=r"(r[0]), "=r"(r[1]), "=r"(r[2]), "=r"(r[3]) : "r"(a));
}
__device__ __forceinline__ void ldsm4t(uint32_t* r, uint32_t a) {
    asm volatile("ldmatrix.sync.aligned.m8n8.x4.trans.shared.b16 {%0,%1,%2,%3}, [%4];\n"
                 : "=r"(r[0]), "=r"(r[1]), "=r"(r[2]), "=r"(r[3]) : "r"(a));
}
// fp32 -> bf16 hi + residual lo (hi+lo carries 16 mantissa bits; products exact)
__device__ __forceinline__ void split2(float f, __nv_bfloat16& h, __nv_bfloat16& l) {
    h = __float2bfloat16(f);
    l = __float2bfloat16(f - __bfloat162float(h));
}
__device__ __forceinline__ void store4(__nv_bfloat16* H, __nv_bfloat16* L, int base, float4 v) {
    __nv_bfloat16 h0,l0,h1,l1,h2,l2,h3,l3;
    split2(v.x,h0,l0); split2(v.y,h1,l1); split2(v.z,h2,l2); split2(v.w,h3,l3);
    __nv_bfloat162 a; a.x=h0; a.y=h1; __nv_bfloat162 b; b.x=h2; b.y=h3;
    __nv_bfloat162 c; c.x=l0; c.y=l1; __nv_bfloat162 d; d.x=l2; d.y=l3;
    *(__nv_bfloat162*)(H + base)     = a;
    *(__nv_bfloat162*)(H + base + 2) = b;
    *(__nv_bfloat162*)(L + base)     = c;
    *(__nv_bfloat162*)(L + base + 2) = d;
}

// NT mma phase over one BK=32 smem tile: A[128][32] x B[64][32] -> d[2][4][4]
__device__ __forceinline__ void mma_phase_nt(
    const __nv_bfloat16* Ah, const __nv_bfloat16* Al,
    const __nv_bfloat16* Bh, const __nv_bfloat16* Bl,
    int wm, int wn, int lane, float d[2][4][4])
{
#pragma unroll
    for (int ks = 0; ks < 32; ks += 16) {
        uint32_t ah[2][4], al[2][4], bh[4][2], bl[4][2];
#pragma unroll
        for (int i = 0; i < 2; i++) {
            int row = wm + i * 16 + (lane & 15);
            int col = ks + (lane >> 4) * 8;
            uint32_t off = (uint32_t)(row * AP + col) * 2;
            ldsm4(ah[i], s2u(Ah) + off);
            ldsm4(al[i], s2u(Al) + off);
        }
#pragma unroll
        for (int jp = 0; jp < 2; jp++) {
            int g = lane >> 3;
            int row = wn + jp * 16 + (g >> 1) * 8 + (lane & 7);
            int col = ks + (g & 1) * 8;
            uint32_t off = (uint32_t)(row * AP + col) * 2;
            uint32_t t[4];
            ldsm4(t, s2u(Bh) + off);
            bh[2*jp][0] = t[0]; bh[2*jp][1] = t[1];
            bh[2*jp+1][0] = t[2]; bh[2*jp+1][1] = t[3];
            ldsm4(t, s2u(Bl) + off);
            bl[2*jp][0] = t[0]; bl[2*jp][1] = t[1];
            bl[2*jp+1][0] = t[2]; bl[2*jp+1][1] = t[3];
        }
#pragma unroll
        for (int i = 0; i < 2; i++)
#pragma unroll
            for (int j = 0; j < 4; j++) {
                mma16816(d[i][j], ah[i], bh[j]);
                mma16816(d[i][j], ah[i], bl[j]);
                mma16816(d[i][j], al[i], bh[j]);
            }
    }
}

// ---------------------------------------------------------------------------
// Projection GEMM via tensor cores (register-prefetch pipelined):
// out[r,j] = sum_c A[r,c] * W[j,c] + bias[j]    (M=8192, N=640, K=640)
// ---------------------------------------------------------------------------
__global__ __launch_bounds__(256, 2) void gemm_proj_tc(
    const float* __restrict__ A, const float* __restrict__ W,
    const float* __restrict__ bias, float* __restrict__ out)
{
    __shared__ __nv_bfloat16 Ah[128 * AP], Al[128 * AP];
    __shared__ __nv_bfloat16 Bh[64 * AP],  Bl[64 * AP];
    const int tid = threadIdx.x;
    const int m0 = blockIdx.y * 128, n0 = blockIdx.x * 64;
    const int lane = tid & 31, warp = tid >> 5;
    const int wm = (warp & 3) * 32, wn = (warp >> 2) * 32;

    float d[2][4][4];
#pragma unroll
    for (int i = 0; i < 2; i++)
#pragma unroll
        for (int j = 0; j < 4; j++)
#pragma unroll
            for (int e = 0; e < 4; e++) d[i][j][e] = 0.f;

    const int ar = tid >> 1, ak = (tid & 1) * 16;
    const int br = tid >> 2, bk = (tid & 3) * 8;
    const float* Ap = A + (size_t)(m0 + ar) * CC + ak;
    const float* Bp = W + (size_t)(n0 + br) * CC + bk;

    float4 aS[4], bS[2];
#pragma unroll
    for (int i = 0; i < 4; i++) aS[i] = *(const float4*)(Ap + i * 4);
#pragma unroll
    for (int i = 0; i < 2; i++) bS[i] = *(const float4*)(Bp + i * 4);

    for (int k0 = 0; k0 < CC; k0 += 32) {
#pragma unroll
        for (int i = 0; i < 4; i++)
            store4(Ah, Al, ar * AP + ak + i * 4, aS[i]);
#pragma unroll
        for (int i = 0; i < 2; i++)
            store4(Bh, Bl, br * AP + bk + i * 4, bS[i]);
        __syncthreads();
        if (k0 + 32 < CC) {
#pragma unroll
            for (int i = 0; i < 4; i++) aS[i] = *(const float4*)(Ap + k0 + 32 + i * 4);
#pragma unroll
            for (int i = 0; i < 2; i++) bS[i] = *(const float4*)(Bp + k0 + 32 + i * 4);
        }
        mma_phase_nt(Ah, Al, Bh, Bl, wm, wn, lane, d);
        __syncthreads();
    }

#pragma unroll
    for (int i = 0; i < 2; i++) {
        int r0 = m0 + wm + i * 16 + (lane >> 2);
#pragma unroll
        for (int j = 0; j < 4; j++) {
            int c = n0 + wn + j * 8 + (lane & 3) * 2;
            float2 bi = *(const float2*)(bias + c);
            float2 o0 = { d[i][j][0] + bi.x, d[i][j][1] + bi.y };
            float2 o1 = { d[i][j][2] + bi.x, d[i][j][3] + bi.y };
            *(float2*)(out + (size_t)r0 * CC + c)       = o0;
            *(float2*)(out + (size_t)(r0 + 8) * CC + c) = o1;
        }
    }
}

// ---------------------------------------------------------------------------
// sim GEMM: sim[b,m,n] = sum_c k[b,m,c]*q[n,b,c];  Kx = exp((sim-1)/eps)
// ---------------------------------------------------------------------------
__global__ __launch_bounds__(256, 2) void gemm_sim_tc(
    const float* __restrict__ kb, const float* __restrict__ qb,
    float* __restrict__ sim, float* __restrict__ Kx)
{
    __shared__ __nv_bfloat16 Ah[128 * AP], Al[128 * AP];
    __shared__ __nv_bfloat16 Bh[64 * AP],  Bl[64 * AP];
    const int b = blockIdx.z;
    const int tid = threadIdx.x;
    const int m0 = blockIdx.y * 128, n0 = blockIdx.x * 64;
    const int lane = tid & 31, warp = tid >> 5;
    const int wm = (warp & 3) * 32, wn = (warp >> 2) * 32;

    float d[2][4][4];
#pragma unroll
    for (int i = 0; i < 2; i++)
#pragma unroll
        for (int j = 0; j < 4; j++)
#pragma unroll
            for (int e = 0; e < 4; e++) d[i][j][e] = 0.f;

    const int ar = tid >> 1, ak = (tid & 1) * 16;
    const int br = tid >> 2, bk = (tid & 3) * 8;
    const float* Ap = kb + ((size_t)b * MM + m0 + ar) * CC + ak;
    const float* Bp = qb + (size_t)(n0 + br) * (BB * CC) + (size_t)b * CC + bk;

    float4 aS[4], bS[2];
#pragma unroll
    for (int i = 0; i < 4; i++) aS[i] = *(const float4*)(Ap + i * 4);
#pragma unroll
    for (int i = 0; i < 2; i++) bS[i] = *(const float4*)(Bp + i * 4);

    for (int k0 = 0; k0 < CC; k0 += 32) {
#pragma unroll
        for (int i = 0; i < 4; i++)
            store4(Ah, Al, ar * AP + ak + i * 4, aS[i]);
#pragma unroll
        for (int i = 0; i < 2; i++)
            store4(Bh, Bl, br * AP + bk + i * 4, bS[i]);
        __syncthreads();
        if (k0 + 32 < CC) {
#pragma unroll
            for (int i = 0; i < 4; i++) aS[i] = *(const float4*)(Ap + k0 + 32 + i * 4);
#pragma unroll
            for (int i = 0; i < 2; i++) bS[i] = *(const float4*)(Bp + k0 + 32 + i * 4);
        }
        mma_phase_nt(Ah, Al, Bh, Bl, wm, wn, lane, d);
        __syncthreads();
    }

#pragma unroll
    for (int i = 0; i < 2; i++) {
        int m = m0 + wm + i * 16 + (lane >> 2);
#pragma unroll
        for (int j = 0; j < 4; j++) {
            int n = n0 + wn + j * 8 + (lane & 3) * 2;
            size_t o0 = ((size_t)b * MM + m) * NQ + n;
            size_t o1 = ((size_t)b * MM + m + 8) * NQ + n;
            float2 s0 = { d[i][j][0], d[i][j][1] };
            float2 s1 = { d[i][j][2], d[i][j][3] };
            *(float2*)(sim + o0) = s0;
            *(float2*)(sim + o1) = s1;
            float2 k0v = { expf((s0.x - 1.0f) / EPS_OT), expf((s0.y - 1.0f) / EPS_OT) };
            float2 k1v = { expf((s1.x - 1.0f) / EPS_OT), expf((s1.y - 1.0f) / EPS_OT) };
            *(float2*)(Kx + o0) = k0v;
            *(float2*)(Kx + o1) = k1v;
        }
    }
}

// ---------------------------------------------------------------------------
// x GEMM: x[n,b,c] = b[n] * sum_m (a[m]*Kx[b,m,n]) * v[b,m,c]
// ---------------------------------------------------------------------------
__global__ __launch_bounds__(256, 2) void gemm_x_tc(
    const float* __restrict__ Kx, const float* __restrict__ v,
    const float* __restrict__ a, const float* __restrict__ bvec,
    float* __restrict__ x)
{
    __shared__ __nv_bfloat16 Ah[32 * XAP], Al[32 * XAP];   // [m][n] natural
    __shared__ __nv_bfloat16 Bh[32 * XBP], Bl[32 * XBP];   // [m][c] natural
    const int b = blockIdx.z;
    const int tid = threadIdx.x;
    const int n0 = blockIdx.y * 128, c0 = blockIdx.x * 64;
    const int lane = tid & 31, warp = tid >> 5;
    const int wm = (warp & 3) * 32, wn = (warp >> 2) * 32;

    float d[2][4][4];
#pragma unroll
    for (int i = 0; i < 2; i++)
#pragma unroll
        for (int j = 0; j < 4; j++)
#pragma unroll
            for (int e = 0; e < 4; e++) d[i][j][e] = 0.f;

    const int amm = tid >> 3, ann = (tid & 7) * 16;   // A: 32 m-rows x 128 n
    const int bmm = tid >> 3, bcc = (tid & 7) * 8;    // B: 32 m-rows x 64 c

    float4 aS[4], bS[2];
    float amS = a[b * MM + amm];
    {
        const float* Ap0 = Kx + ((size_t)b * MM + amm) * NQ + n0 + ann;
        const float* Bp0 = v  + ((size_t)b * MM + bmm) * CC + c0 + bcc;
#pragma unroll
        for (int i = 0; i < 4; i++) aS[i] = *(const float4*)(Ap0 + i * 4);
#pragma unroll
        for (int i = 0; i < 2; i++) bS[i] = *(const float4*)(Bp0 + i * 4);
    }

    for (int m0k = 0; m0k < MM; m0k += 32) {
        const float am = amS;
#pragma unroll
        for (int i = 0; i < 4; i++) {
            float4 vv = aS[i];
            vv.x *= am; vv.y *= am; vv.z *= am; vv.w *= am;
            store4(Ah, Al, amm * XAP + ann + i * 4, vv);
        }
#pragma unroll
        for (int i = 0; i < 2; i++)
            store4(Bh, Bl, bmm * XBP + bcc + i * 4, bS[i]);
        __syncthreads();

        if (m0k + 32 < MM) {
            amS = a[b * MM + m0k + 32 + amm];
            const float* Ap = Kx + ((size_t)b * MM + m0k + 32 + amm) * NQ + n0 + ann;
            const float* Bp = v  + ((size_t)b * MM + m0k + 32 + bmm) * CC + c0 + bcc;
#pragma unroll
            for (int i = 0; i < 4; i++) aS[i] = *(const float4*)(Ap + i * 4);
#pragma unroll
            for (int i = 0; i < 2; i++) bS[i] = *(const float4*)(Bp + i * 4);
        }

#pragma unroll
        for (int ks = 0; ks < 32; ks += 16) {
            uint32_t ah[2][4], al[2][4], bh[4][2], bl[4][2];
#pragma unroll
            for (int i = 0; i < 2; i++) {
                int row = ks + (lane & 7) + ((lane >> 4) << 3);
                int col = wm + i * 16 + ((lane >> 3) & 1) * 8;
                uint32_t off = (uint32_t)(row * XAP + col) * 2;
                ldsm4t(ah[i], s2u(Ah) + off);
                ldsm4t(al[i], s2u(Al) + off);
            }
#pragma unroll
            for (int jp = 0; jp < 2; jp++) {
                int g = lane >> 3;
                int row = ks + (g & 1) * 8 + (lane & 7);
                int col = wn + jp * 16 + (g >> 1) * 8;
                uint32_t off = (uint32_t)(row * XBP + col) * 2;
                uint32_t t[4];
                ldsm4t(t, s2u(Bh) + off);
                bh[2*jp][0] = t[0]; bh[2*jp][1] = t[1];
                bh[2*jp+1][0] = t[2]; bh[2*jp+1][1] = t[3];
                ldsm4t(t, s2u(Bl) + off);
                bl[2*jp][0] = t[0]; bl[2*jp][1] = t[1];
                bl[2*jp+1][0] = t[2]; bl[2*jp+1][1] = t[3];
            }
#pragma unroll
            for (int i = 0; i < 2; i++)
#pragma unroll
                for (int j = 0; j < 4; j++) {
                    mma16816(d[i][j], ah[i], bh[j]);
                    mma16816(d[i][j], ah[i], bl[j]);
                    mma16816(d[i][j], al[i], bh[j]);
                }
        }
        __syncthreads();
    }

#pragma unroll
    for (int i = 0; i < 2; i++) {
        int n = n0 + wm + i * 16 + (lane >> 2);
        float bn0 = bvec[b * NQ + n];
        float bn1 = bvec[b * NQ + n + 8];
#pragma unroll
        for (int j = 0; j < 4; j++) {
            int c = c0 + wn + j * 8 + (lane & 3) * 2;
            float2 o0 = { d[i][j][0] * bn0, d[i][j][1] * bn0 };
            float2 o1 = { d[i][j][2] * bn1, d[i][j][3] * bn1 };
            *(float2*)(x + ((size_t)n * BB + b) * CC + c)       = o0;
            *(float2*)(x + ((size_t)(n + 8) * BB + b) * CC + c) = o1;
        }
    }
}

// ---------------------------------------------------------------------------
// l2norm over each 640-element row, in place. One warp per row.
// ---------------------------------------------------------------------------
__global__ __launch_bounds__(256) void l2norm_rows(float* __restrict__ buf)
{
    const int row  = blockIdx.x * 8 + (threadIdx.x >> 5);
    const int lane = threadIdx.x & 31;
    float4* p = (float4*)(buf + (size_t)row * CC);
    float4 vals[5];
    float ss = 0.f;
#pragma unroll
    for (int i = 0; i < 5; i++) {
        vals[i] = p[lane + i * 32];
        ss += vals[i].x*vals[i].x + vals[i].y*vals[i].y
            + vals[i].z*vals[i].z + vals[i].w*vals[i].w;
    }
#pragma unroll
    for (int o = 16; o; o >>= 1) ss += __shfl_xor_sync(0xffffffffu, ss, o);
    float inv = 1.0f / fmaxf(sqrtf(ss), 1e-12f);
#pragma unroll
    for (int i = 0; i < 5; i++) {
        float4 v = vals[i];
        v.x *= inv; v.y *= inv; v.z *= inv; v.w *= inv;
        p[lane + i * 32] = v;
    }
}

// ---------------------------------------------------------------------------
// Sinkhorn prep (mask = int32); zeroes a; seeds part so that the first
// fused launch's b-recompute yields b = nuP / nuP = 1.
// ---------------------------------------------------------------------------
__global__ __launch_bounds__(1024) void prep(
    const int* __restrict__ mask,
    float* __restrict__ muP,
    float* __restrict__ bvec,
    float* __restrict__ a,
    float* __restrict__ part)
{
    const int b = blockIdx.x;
    const int m = threadIdx.x;
    int v = (mask[b * MM + m] != 0) ? 1 : 0;
    __shared__ int red[32];
    __shared__ int total;
    int s = v;
#pragma unroll
    for (int o = 16; o; o >>= 1) s += __shfl_xor_sync(0xffffffffu, s, o);
    if ((m & 31) == 0) red[m >> 5] = s;
    __syncthreads();
    if (m < 32) {
        int t = red[m];
#pragma unroll
        for (int o = 16; o; o >>= 1) t += __shfl_xor_sync(0xffffffffu, t, o);
        if (m == 0) total = t;
    }
    __syncthreads();
    int cnt = total;
    const float nuP = 1.0f / (float)NQ + 1e-8f;
    muP[b * MM + m]  = v ? (1.0f / (float)cnt + 1e-8f) : 0.0f;
    bvec[b * MM + m] = 1.0f;
    a[b * MM + m]    = 0.0f;
#pragma unroll
    for (int p = 0; p < SPB; p++)
        part[(size_t)(b * SPB + p) * NQ + m] = (p == 0) ? nuP : 0.0f;
}

// ---------------------------------------------------------------------------
// Fused Sinkhorn iteration, ONE launch per iteration:
//   Phase A: recompute b[n] = nuP / sum_p part[p][n] in smem (all blocks)
//   Phase B: per live row m: s = <K_m, b>; a[m] = mu/s; colpart += a[m]*K_m
//   Phase C: staged 16->8->1 smem reduction, write per-block partials.
// Grid = 128 blocks (16 per batch, 64 rows each) x 512 threads -> 1 wave.
// ---------------------------------------------------------------------------
__global__ __launch_bounds__(512) void sink_fused(
    const float* __restrict__ Kx,
    const float* __restrict__ muP,
    float* __restrict__ a,
    float* __restrict__ part)
{
    __shared__ float bs[NQ];
    __shared__ float wpart[8][NQ];
    const int blk  = blockIdx.x;
    const int b    = blk >> 4;          // 16 blocks per batch
    const int sub  = blk & 15;
    const int tid  = threadIdx.x;
    const int warp = tid >> 5, lane = tid & 31;
    const float nuP = 1.0f / (float)NQ + 1e-8f;

    // ---- Phase A: b from previous partials (identical in every block) ----
    {
        const float* p0 = part + (size_t)(b * SPB) * NQ;
#pragma unroll
        for (int h = 0; h < 2; h++) {
            int col = tid + h * 512;
            float t = 0.f;
#pragma unroll
            for (int p = 0; p < SPB; p++) t += p0[(size_t)p * NQ + col];
            bs[col] = (t > 0.f) ? (nuP / t) : 0.f;
        }
    }
    __syncthreads();

    // ---- Phase B: row pass over this block's 64 rows ----
    float4 acc[8];
#pragma unroll
    for (int i = 0; i < 8; i++) acc[i] = make_float4(0.f, 0.f, 0.f, 0.f);

#pragma unroll
    for (int rr = 0; rr < 4; rr++) {
        const int m = sub * 64 + warp * 4 + rr;
        const float mu = muP[b * MM + m];
        if (mu != 0.f) {
            const float4* row = (const float4*)(Kx + ((size_t)b * MM + m) * NQ);
            float4 kv[8];
            float s = 0.f;
#pragma unroll
            for (int i = 0; i < 8; i++) {
                kv[i] = row[lane + i * 32];
                float4 bv = ((const float4*)bs)[lane + i * 32];
                s += kv[i].x*bv.x + kv[i].y*bv.y + kv[i].z*bv.z + kv[i].w*bv.w;
            }
#pragma unroll
            for (int o = 16; o; o >>= 1) s += __shfl_xor_sync(0xffffffffu, s, o);
            const float av = mu / s;
            if (lane == 0) a[b * MM + m] = av;
#pragma unroll
            for (int i = 0; i < 8; i++) {
                acc[i].x += av * kv[i].x;
                acc[i].y += av * kv[i].y;
                acc[i].z += av * kv[i].z;
                acc[i].w += av * kv[i].w;
            }
        }
    }

    // ---- Phase C: staged reduction 16 warps -> 8 buffers -> partial ----
    if (warp < 8) {
#pragma unroll
        for (int i = 0; i < 8; i++)
            ((float4*)wpart[warp])[lane + i * 32] = acc[i];
    }
    __syncthreads();
    if (warp >= 8) {
#pragma unroll
        for (int i = 0; i < 8; i++) {
            float4 u = ((const float4*)wpart[warp - 8])[lane + i * 32];
            u.x += acc[i].x; u.y += acc[i].y; u.z += acc[i].z; u.w += acc[i].w;
            ((float4*)wpart[warp - 8])[lane + i * 32] = u;
        }
    }
    __syncthreads();
    if (tid < 256) {
        float4 t = ((const float4*)wpart[0])[tid];
#pragma unroll
        for (int w = 1; w < 8; w++) {
            float4 u = ((const float4*)wpart[w])[tid];
            t.x += u.x; t.y += u.y; t.z += u.z; t.w += u.w;
        }
        ((float4*)(part + (size_t)blk * NQ))[tid] = t;
    }
}

// ---------------------------------------------------------------------------
// Final b materialization: b[b,n] = nuP / sum_p part[b*SPB+p][n]
// ---------------------------------------------------------------------------
__global__ __launch_bounds__(256) void sink_finalize(
    const float* __restrict__ part,
    float* __restrict__ bvec)
{
    const int b   = blockIdx.x >> 2;
    const int col = (blockIdx.x & 3) * 256 + threadIdx.x;
    const float nuP = 1.0f / (float)NQ + 1e-8f;
    const float* p = part + (size_t)(b * SPB) * NQ + col;
    float t = 0.f;
#pragma unroll
    for (int s = 0; s < SPB; s++) t += p[(size_t)s * NQ];
    bvec[b * NQ + col] = (t > 0.f) ? (nuP / t) : 0.f;
}

// ---------------------------------------------------------------------------
// attn_save[b,m] = mask ? M*Nq * a[m] * sum_n sim*Kx*b[n] : 0
// ---------------------------------------------------------------------------
__global__ __launch_bounds__(256) void attn_kernel(
    const float* __restrict__ sim,
    const float* __restrict__ Kx,
    const float* __restrict__ a,
    const float* __restrict__ bvec,
    const float* __restrict__ muP,
    float* __restrict__ out_attn)
{
    __shared__ float bs[NQ];
    const int blk = blockIdx.x;
    const int b   = blk >> 7;
    const int m   = (blk & 127) * 8 + (threadIdx.x >> 5);
    const int lane = threadIdx.x & 31;
    ((float4*)bs)[threadIdx.x] = ((const float4*)(bvec + b * NQ))[threadIdx.x];
    __syncthreads();
    float mu  = muP[b * MM + m];
    float val = 0.f;
    if (mu != 0.f) {
        size_t off = ((size_t)b * MM + m) * NQ;
        const float4* srow = (const float4*)(sim + off);
        const float4* krow = (const float4*)(Kx + off);
        float s = 0.f;
#pragma unroll
        for (int i = 0; i < 8; i++) {
            float4 sv = srow[lane + i * 32];
            float4 kv = krow[lane + i * 32];
            float4 bv = ((const float4*)bs)[lane + i * 32];
            s += sv.x*kv.x*bv.x + sv.y*kv.y*bv.y + sv.z*kv.z*bv.z + sv.w*kv.w*bv.w;
        }
#pragma unroll
        for (int o = 16; o; o >>= 1) s += __shfl_xor_sync(0xffffffffu, s, o);
        val = (float)(MM) * (float)(NQ) * a[b * MM + m] * s;
    }
    if (lane == 0) out_attn[b * MM + m] = val;
}

// ---------------------------------------------------------------------------
extern "C" void kernel_launch(void* const* d_in, const int* in_sizes, int n_in,
                              void* d_out, int out_size)
{
    const float* xq = (const float*)d_in[0];
    const float* xk = (const float*)d_in[1];
    const float* xv = (const float*)d_in[2];
    const int*   mask = (const int*)d_in[3];
    const float* Wq = (const float*)d_in[4];
    const float* bq = (const float*)d_in[5];
    const float* Wk = (const float*)d_in[6];
    const float* bk = (const float*)d_in[7];
    const float* Wv = (const float*)d_in[8];
    const float* bv = (const float*)d_in[9];
    const float* Wp = (const float*)d_in[10];
    const float* bp = (const float*)d_in[11];

    float* out  = (float*)d_out;
    float* attn = out + (size_t)RR * CC;

    float *q, *k, *v, *x, *sim, *Kx, *a, *b, *mu, *part;
    cudaGetSymbolAddress((void**)&q,    g_q);
    cudaGetSymbolAddress((void**)&k,    g_k);
    cudaGetSymbolAddress((void**)&v,    g_v);
    cudaGetSymbolAddress((void**)&x,    g_x);
    cudaGetSymbolAddress((void**)&sim,  g_sim);
    cudaGetSymbolAddress((void**)&Kx,   g_Kx);
    cudaGetSymbolAddress((void**)&a,    g_a);
    cudaGetSymbolAddress((void**)&b,    g_b);
    cudaGetSymbolAddress((void**)&mu,   g_mu);
    cudaGetSymbolAddress((void**)&part, g_part);

    dim3 gP(CC / 64, RR / 128);   // (10, 64)

    gemm_proj_tc<<<gP, 256>>>(xq, Wq, bq, q);
    gemm_proj_tc<<<gP, 256>>>(xk, Wk, bk, k);
    gemm_proj_tc<<<gP, 256>>>(xv, Wv, bv, v);
    l2norm_rows<<<RR / 8, 256>>>(q);
    l2norm_rows<<<RR / 8, 256>>>(k);
    prep<<<BB, 1024>>>(mask, mu, b, a, part);

    gemm_sim_tc<<<dim3(NQ / 64, MM / 128, BB), 256>>>(k, q, sim, Kx);

    for (int it = 0; it < N_ITERS; it++)
        sink_fused<<<BB * SPB, 512>>>(Kx, mu, a, part);
    sink_finalize<<<32, 256>>>(part, b);

    attn_kernel<<<(BB * MM) / 8, 256>>>(sim, Kx, a, b, mu, attn);
    gemm_x_tc<<<dim3(CC / 64, NQ / 128, BB), 256>>>(Kx, v, a, b, x);
    gemm_proj_tc<<<gP, 256>>>(x, Wp, bp, out);
}